// round 12
// baseline (speedup 1.0000x reference)
#include <cuda_runtime.h>
#include <cuda_bf16.h>
#include <cstdint>
#include <cstddef>

#define Nn 50000
#define Ee 300000
#define DH 256
#define NB 196          // ceil(Nn/256)
#define NRB 391         // ceil(Nn/128) row blocks
#define SLOT ((size_t)NRB * 32768)   // bf16 elements per A-split slot

// ================= helpers =================
__device__ __forceinline__ uint32_t smem_to_u32(const void* p) {
    uint32_t a;
    asm("{ .reg .u64 t; cvta.to.shared.u64 t, %1; cvt.u32.u64 %0, t; }" : "=r"(a) : "l"(p));
    return a;
}
__device__ __forceinline__ void ldsm4(uint32_t* r, uint32_t addr) {
    asm volatile("ldmatrix.sync.aligned.m8n8.x4.shared.b16 {%0,%1,%2,%3}, [%4];"
        : "=r"(r[0]), "=r"(r[1]), "=r"(r[2]), "=r"(r[3]) : "r"(addr));
}
__device__ __forceinline__ void ldsm2(uint32_t* r, uint32_t addr) {
    asm volatile("ldmatrix.sync.aligned.m8n8.x2.shared.b16 {%0,%1}, [%2];"
        : "=r"(r[0]), "=r"(r[1]) : "r"(addr));
}
__device__ __forceinline__ void mma16816(float* c, const uint32_t* a, const uint32_t* b) {
    asm volatile("mma.sync.aligned.m16n8k16.row.col.f32.bf16.bf16.f32 "
        "{%0,%1,%2,%3}, {%4,%5,%6,%7}, {%8,%9}, {%0,%1,%2,%3};"
        : "+f"(c[0]), "+f"(c[1]), "+f"(c[2]), "+f"(c[3])
        : "r"(a[0]), "r"(a[1]), "r"(a[2]), "r"(a[3]), "r"(b[0]), "r"(b[1]));
}
#define CP_ASYNC16(sa, gp) \
    asm volatile("cp.async.cg.shared.global [%0], [%1], 16;" :: "r"(sa), "l"(gp))
#define CP_COMMIT() asm volatile("cp.async.commit_group;")
#define CP_WAIT0()  asm volatile("cp.async.wait_group 0;")
#define SMEM_SWZ(o) ((o) ^ ((((uint32_t)(o)) >> 3) & 0x70u))

__device__ __forceinline__ void split4(float4 v, uint2& hi, uint2& lo) {
    __nv_bfloat162 h0, h1, l0, l1;
    h0.x = __float2bfloat16(v.x);  h0.y = __float2bfloat16(v.y);
    h1.x = __float2bfloat16(v.z);  h1.y = __float2bfloat16(v.w);
    l0.x = __float2bfloat16(v.x - __bfloat162float(h0.x));
    l0.y = __float2bfloat16(v.y - __bfloat162float(h0.y));
    l1.x = __float2bfloat16(v.z - __bfloat162float(h1.x));
    l1.y = __float2bfloat16(v.w - __bfloat162float(h1.y));
    hi.x = *(uint32_t*)&h0;  hi.y = *(uint32_t*)&h1;
    lo.x = *(uint32_t*)&l0;  lo.y = *(uint32_t*)&l1;
}

// ================= scratch (static device globals) =================
__device__ float g_h   [(size_t)Nn * DH];        // fp32 h (residual path)
__device__ float g_h1  [3 * (size_t)Nn * DH];    // per-hop GEMM output
__device__ float g_acc3[3 * (size_t)Nn * DH];    // per-hop dec output
__device__ float g_as [3 * (size_t)Nn * 8];
__device__ float g_ad [3 * (size_t)Nn * 8];
__device__ float g_bw [6 * 256];                 // folded dec column bias
// weights: 13 matrices, [4 kc][256 n][64 k] bf16 swizzled
__device__ __nv_bfloat16 g_bh[13 * 65536];
__device__ __nv_bfloat16 g_bl[13 * 65536];
// A splits: h (1 slot) + x/agg (3 slots, per hop)
__device__ __nv_bfloat16 g_hh[SLOT];
__device__ __nv_bfloat16 g_hl[SLOT];
__device__ __nv_bfloat16 g_gh[3 * SLOT];
__device__ __nv_bfloat16 g_gl[3 * SLOT];
// CSR (by dst)
__device__ int g_deg [3][Nn];
__device__ int g_rp  [3][Nn];
__device__ int g_csrc[3][Ee];
__device__ int g_cur [3][Nn];
__device__ int g_bsum[3][256];

// ---------------- weight convert ----------------
__global__ void convw_kernel(const float* __restrict__ W, int nmat, int gbase)
{
    int id = blockIdx.x * blockDim.x + threadIdx.x;
    if (id >= nmat * 65536) return;
    int g = id >> 16;
    int r = id & 65535;
    int n = r & 255;
    int kf = r >> 8;
    float v = W[(size_t)g * 65536 + (size_t)kf * 256 + n];
    __nv_bfloat16 hi = __float2bfloat16(v);
    __nv_bfloat16 lo = __float2bfloat16(v - __bfloat162float(hi));
    int kc = kf >> 6, kk = kf & 63;
    uint32_t off = (uint32_t)kc * 32768u + SMEM_SWZ((uint32_t)(n * 128 + kk * 2));
    size_t base = (size_t)(gbase + g) * 131072u;
    *(__nv_bfloat16*)((char*)g_bh + base + off) = hi;
    *(__nv_bfloat16*)((char*)g_bl + base + off) = lo;
}

// ---------------- x split into slot 0 of g_gh/g_gl ----------------
__global__ void conva_kernel(const float* __restrict__ A)
{
    int id = blockIdx.x * blockDim.x + threadIdx.x;
    if (id >= Nn * 64) return;
    int r = id >> 6, q = id & 63;
    float4 v = *(const float4*)(A + (size_t)r * 256 + q * 4);
    uint2 hi, lo;
    split4(v, hi, lo);
    int rb = r >> 7, rloc = r & 127;
    int kc = q >> 4, kk = (q & 15) * 4;
    size_t off = ((size_t)rb * 4 + kc) * 16384 + SMEM_SWZ((uint32_t)(rloc * 128 + kk * 2));
    *(uint2*)((char*)g_gh + off) = hi;
    *(uint2*)((char*)g_gl + off) = lo;
}

// ---------------- folded dec bias accumulate: g_bw += gat_bias @ dec_w ----------
__global__ void biasw_acc(const float* __restrict__ gat_bias,
                          const float* __restrict__ dec_w)
{
    int lk = blockIdx.x;
    int n = threadIdx.x;
    int k0 = blockIdx.y * 32;
    const float* W = dec_w + (size_t)lk * 65536;
    const float* gb = gat_bias + lk * 256;
    float acc = 0.f;
#pragma unroll
    for (int k = 0; k < 32; k++) acc += gb[k0 + k] * W[(k0 + k) * 256 + n];
    atomicAdd(&g_bw[lk * 256 + n], acc);
}

// ---------------- CSR build (all 3 hops batched via blockIdx.y) ----------------
__global__ void hist3(const int* __restrict__ edges)
{
    int hop = blockIdx.y;
    int e = blockIdx.x * blockDim.x + threadIdx.x;
    if (e < Ee) atomicAdd(&g_deg[hop][edges[(size_t)hop * 2 * Ee + Ee + e]], 1);
}
__global__ void bsum3()
{
    __shared__ int ws[8];
    int hop = blockIdx.y;
    int i = blockIdx.x * 256 + threadIdx.x;
    int v = (i < Nn) ? g_deg[hop][i] : 0;
#pragma unroll
    for (int o = 16; o > 0; o >>= 1) v += __shfl_xor_sync(0xffffffffu, v, o);
    if ((threadIdx.x & 31) == 0) ws[threadIdx.x >> 5] = v;
    __syncthreads();
    if (threadIdx.x < 8) {
        int x = ws[threadIdx.x];
#pragma unroll
        for (int o = 4; o > 0; o >>= 1) x += __shfl_xor_sync(0xffu, x, o);
        if (threadIdx.x == 0) g_bsum[hop][blockIdx.x] = x;
    }
}
__global__ void bscan3()   // grid 3: exclusive scan per hop
{
    __shared__ int sh[256];
    int hop = blockIdx.x;
    int t = threadIdx.x;
    int orig = (t < NB) ? g_bsum[hop][t] : 0;
    sh[t] = orig;
    __syncthreads();
#pragma unroll
    for (int o = 1; o < 256; o <<= 1) {
        int v = (t >= o) ? sh[t - o] : 0;
        __syncthreads();
        sh[t] += v;
        __syncthreads();
    }
    if (t < NB) g_bsum[hop][t] = sh[t] - orig;
}
__global__ void rowptr3()
{
    __shared__ int sh[256];
    int hop = blockIdx.y;
    int t = threadIdx.x;
    int i = blockIdx.x * 256 + t;
    int d = (i < Nn) ? g_deg[hop][i] : 0;
    sh[t] = d;
    __syncthreads();
#pragma unroll
    for (int o = 1; o < 256; o <<= 1) {
        int v = (t >= o) ? sh[t - o] : 0;
        __syncthreads();
        sh[t] += v;
        __syncthreads();
    }
    if (i < Nn) {
        int rp = g_bsum[hop][blockIdx.x] + sh[t] - d;
        g_rp[hop][i] = rp;
        g_cur[hop][i] = rp;
    }
}
__global__ void fill3(const int* __restrict__ edges)
{
    int hop = blockIdx.y;
    int e = blockIdx.x * blockDim.x + threadIdx.x;
    if (e >= Ee) return;
    const int* src = edges + (size_t)hop * 2 * Ee;
    const int* dst = src + Ee;
    int pos = atomicAdd(&g_cur[hop][dst[e]], 1);
    g_csrc[hop][pos] = src[e];
}

// ---------------- GEMM (multi-hop via blockIdx.y; B double-buffered) ----------
// grid (NRB, 2*nhop): hop = blockIdx.y>>1, colBase = (blockIdx.y&1)*128
// mode bit0: leaky(0.01); bit2: emit alphas; bit3: write h split;
// bit4: per-hop bbias (bbias += hop*256); A slot per hop when aHop!=0
#define SM_AH 0
#define SM_AL 16384
#define SM_B0 32768
#define SM_B1 65536
#define SM_TOTAL 98304

__global__ void __launch_bounds__(256, 2) gemm_mma(
    const __nv_bfloat16* __restrict__ Ah, const __nv_bfloat16* __restrict__ Al,
    int aHop, int gidxBase, const float* __restrict__ bbias,
    const float* __restrict__ attS, const float* __restrict__ attD,
    float* __restrict__ C, int M, int mode, float scale)
{
    extern __shared__ char smem[];
    const uint32_t sb = smem_to_u32(smem);
    const int tid = threadIdx.x, wid = tid >> 5, lane = tid & 31;
    const int hop = blockIdx.y >> 1;
    const int rowBase = blockIdx.x * 128;
    const int colBase = (blockIdx.y & 1) * 128;
    const int warpM = (wid & 1) * 64;
    const int warpN = (wid >> 1) * 32;

    const char* bh = (const char*)g_bh + (size_t)(gidxBase + hop) * 131072u + (size_t)colBase * 128u;
    const char* bl = (const char*)g_bl + (size_t)(gidxBase + hop) * 131072u + (size_t)colBase * 128u;
    const size_t aoff = (size_t)blockIdx.x * 65536u + (aHop ? (size_t)hop * (SLOT * 2) : 0);
    const char* ah = (const char*)Ah + aoff;
    const char* al = (const char*)Al + aoff;
    C += (size_t)hop * Nn * 256;
    if (mode & 16) bbias += hop * 256;

    float acc[4][4][4];
#pragma unroll
    for (int i = 0; i < 4; i++)
#pragma unroll
        for (int j = 0; j < 4; j++)
#pragma unroll
            for (int c = 0; c < 4; c++) acc[i][j][c] = 0.f;

    const uint32_t xorA = (uint32_t)((lane & 7) << 4);
    const uint32_t aRow = (uint32_t)(warpM + (lane & 15));
    const uint32_t aSel = (uint32_t)((lane >> 4) << 4);
    const uint32_t bRow = (uint32_t)(warpN + (lane & 7));
    const uint32_t bSel = (uint32_t)(((lane >> 3) & 1) << 4);

    // ---- copy helpers ----
    auto cpA = [&](int kc) {
        const char* sah = ah + (size_t)kc * 16384;
        const char* sal = al + (size_t)kc * 16384;
#pragma unroll
        for (int it = 0; it < 4; it++) {
            uint32_t j = (uint32_t)(tid + it * 256) * 16u;
            CP_ASYNC16(sb + SM_AH + j, sah + j);
            CP_ASYNC16(sb + SM_AL + j, sal + j);
        }
    };
    auto cpB = [&](int kc, uint32_t bbase) {
        const char* sbh = bh + (size_t)kc * 32768;
        const char* sbl = bl + (size_t)kc * 32768;
#pragma unroll
        for (int it = 0; it < 4; it++) {     // 16KB BH + 16KB BL per buffer
            uint32_t j = (uint32_t)(tid + it * 256) * 16u;
            CP_ASYNC16(sb + bbase + j, sbh + j);
            CP_ASYNC16(sb + bbase + 16384 + j, sbl + j);
        }
    };

    // ---- prologue: A(0) + B(0) ----
    cpA(0);
    cpB(0, SM_B0);
    CP_COMMIT();
    CP_WAIT0();
    __syncthreads();

    for (int kc = 0; kc < 4; kc++) {
        const uint32_t bbase = (kc & 1) ? SM_B1 : SM_B0;
        if (kc < 3) {
            cpB(kc + 1, bbase ^ (SM_B0 ^ SM_B1));
            CP_COMMIT();
        }
#pragma unroll
        for (int ks = 0; ks < 4; ks++) {
            uint32_t ahf[4][4], alf[4][4], bhf[4][2], blf[4][2];
            const uint32_t kOffA = (uint32_t)(ks * 32) + aSel;
            const uint32_t kOffB = (uint32_t)(ks * 32) + bSel;
#pragma unroll
            for (int i = 0; i < 4; i++) {
                uint32_t off = (((aRow + i * 16) * 128u + kOffA) ^ xorA);
                ldsm4(ahf[i], sb + SM_AH + off);
                ldsm4(alf[i], sb + SM_AL + off);
            }
#pragma unroll
            for (int j = 0; j < 4; j++) {
                uint32_t off = (((bRow + j * 8) * 128u + kOffB) ^ xorA);
                ldsm2(bhf[j], sb + bbase + off);
                ldsm2(blf[j], sb + bbase + 16384 + off);
            }
#pragma unroll
            for (int i = 0; i < 4; i++)
#pragma unroll
                for (int j = 0; j < 4; j++) mma16816(acc[i][j], ahf[i], bhf[j]);
#pragma unroll
            for (int i = 0; i < 4; i++)
#pragma unroll
                for (int j = 0; j < 4; j++) mma16816(acc[i][j], ahf[i], blf[j]);
#pragma unroll
            for (int i = 0; i < 4; i++)
#pragma unroll
                for (int j = 0; j < 4; j++) mma16816(acc[i][j], alf[i], bhf[j]);
        }
        if (kc < 3) {
            __syncthreads();       // all MMA(kc) reads of A buffer done
            cpA(kc + 1);
            CP_COMMIT();
            CP_WAIT0();
            __syncthreads();
        }
    }

    // ---- epilogue ----
    const int tg = lane >> 2;
    const int tc = (lane & 3) * 2;
    const int head = (blockIdx.y & 1) * 4 + (wid >> 1);
#pragma unroll
    for (int i = 0; i < 4; i++) {
        int rloc = warpM + i * 16 + tg;
        int r0 = rowBase + rloc;
        float as0 = 0.f, ad0 = 0.f, as1 = 0.f, ad1 = 0.f;
#pragma unroll
        for (int j = 0; j < 4; j++) {
            int col = colBase + warpN + j * 8 + tc;
            float b0 = bbias ? bbias[col] : 0.f;
            float b1 = bbias ? bbias[col + 1] : 0.f;
            float v0 = acc[i][j][0] + b0, v1 = acc[i][j][1] + b1;
            float v2 = acc[i][j][2] + b0, v3 = acc[i][j][3] + b1;
            if (mode & 1) {
                v0 = (v0 > 0.f) ? v0 : 0.01f * v0;
                v1 = (v1 > 0.f) ? v1 : 0.01f * v1;
                v2 = (v2 > 0.f) ? v2 : 0.01f * v2;
                v3 = (v3 > 0.f) ? v3 : 0.01f * v3;
            }
            v0 *= scale; v1 *= scale; v2 *= scale; v3 *= scale;
            if (r0 < M)
                *(float2*)(C + (size_t)r0 * 256 + col) = make_float2(v0, v1);
            if (r0 + 8 < M)
                *(float2*)(C + (size_t)(r0 + 8) * 256 + col) = make_float2(v2, v3);
            if (mode & 8) {
                int kcq = col >> 6, kk = col & 63;
                size_t tb = ((size_t)blockIdx.x * 4 + kcq) * 16384;
                if (r0 < M) {
                    uint32_t so = SMEM_SWZ((uint32_t)(rloc * 128 + kk * 2));
                    __nv_bfloat162 hp, lp;
                    hp.x = __float2bfloat16(v0); hp.y = __float2bfloat16(v1);
                    lp.x = __float2bfloat16(v0 - __bfloat162float(hp.x));
                    lp.y = __float2bfloat16(v1 - __bfloat162float(hp.y));
                    *(uint32_t*)((char*)g_hh + tb + so) = *(uint32_t*)&hp;
                    *(uint32_t*)((char*)g_hl + tb + so) = *(uint32_t*)&lp;
                }
                if (r0 + 8 < M) {
                    uint32_t so = SMEM_SWZ((uint32_t)((rloc + 8) * 128 + kk * 2));
                    __nv_bfloat162 hp, lp;
                    hp.x = __float2bfloat16(v2); hp.y = __float2bfloat16(v3);
                    lp.x = __float2bfloat16(v2 - __bfloat162float(hp.x));
                    lp.y = __float2bfloat16(v3 - __bfloat162float(hp.y));
                    *(uint32_t*)((char*)g_hh + tb + so) = *(uint32_t*)&hp;
                    *(uint32_t*)((char*)g_hl + tb + so) = *(uint32_t*)&lp;
                }
            }
            if (mode & 4) {
                float s0 = attS[hop * 256 + col], s1 = attS[hop * 256 + col + 1];
                float d0 = attD[hop * 256 + col], d1 = attD[hop * 256 + col + 1];
                as0 += v0 * s0 + v1 * s1;  ad0 += v0 * d0 + v1 * d1;
                as1 += v2 * s0 + v3 * s1;  ad1 += v2 * d0 + v3 * d1;
            }
        }
        if (mode & 4) {
#pragma unroll
            for (int o = 1; o <= 2; o <<= 1) {
                as0 += __shfl_xor_sync(0xffffffffu, as0, o);
                ad0 += __shfl_xor_sync(0xffffffffu, ad0, o);
                as1 += __shfl_xor_sync(0xffffffffu, as1, o);
                ad1 += __shfl_xor_sync(0xffffffffu, ad1, o);
            }
            if ((lane & 3) == 0) {
                size_t ab = (size_t)hop * Nn * 8;
                if (r0 < M)     { g_as[ab + (size_t)r0 * 8 + head] = as0;       g_ad[ab + (size_t)r0 * 8 + head] = ad0; }
                if (r0 + 8 < M) { g_as[ab + (size_t)(r0 + 8) * 8 + head] = as1; g_ad[ab + (size_t)(r0 + 8) * 8 + head] = ad1; }
            }
        }
    }
}

// ---------------- fused softmax + aggregate: warp per dst node, 3 hops batched --
// Pass 1: online softmax stats per head (lane&7 owns one head, 4 replicas).
// Pass 2: recompute alpha inline, gather h1[src], accumulate; write bf16 split.
__global__ void edge_fused3()
{
    int gt = blockIdx.x * blockDim.x + threadIdx.x;
    int d = gt >> 5, lane = gt & 31;
    if (d >= Nn) return;
    int hop = blockIdx.y;
    int start = g_rp[hop][d];
    int end = start + g_deg[hop][d];
    const float* as = g_as + (size_t)hop * Nn * 8;
    const float* ad = g_ad + (size_t)hop * Nn * 8;
    const float* h1 = g_h1 + (size_t)hop * Nn * 256;

    // pass 1: head hh = lane&7
    int hh = lane & 7;
    float adv = ad[(size_t)d * 8 + hh];
    float m = -3.4e38f, sum = 0.f;
    for (int j = start; j < end; j++) {
        int s = g_csrc[hop][j];
        float lg = as[(size_t)s * 8 + hh] + adv;
        lg = (lg > 0.f) ? lg : 0.2f * lg;
        float mn = fmaxf(m, lg);
        sum = sum * __expf(m - mn) + __expf(lg - mn);
        m = mn;
    }

    // broadcast per-head stats to aggregation layout
    int h0 = lane >> 3, h1i = 4 + (lane >> 3);
    float m0 = __shfl_sync(0xffffffffu, m, h0);
    float s0 = __shfl_sync(0xffffffffu, sum, h0);
    float m1 = __shfl_sync(0xffffffffu, m, h1i);
    float s1 = __shfl_sync(0xffffffffu, sum, h1i);
    float inv0 = 1.f / (s0 + 1e-16f);
    float inv1 = 1.f / (s1 + 1e-16f);
    float adv0 = ad[(size_t)d * 8 + h0];
    float adv1 = ad[(size_t)d * 8 + h1i];

    // pass 2: aggregate
    float4 a0 = make_float4(0.f, 0.f, 0.f, 0.f);
    float4 a1 = a0;
    for (int j = start; j < end; j++) {
        int s = g_csrc[hop][j];
        float lg0 = as[(size_t)s * 8 + h0] + adv0;
        float lg1 = as[(size_t)s * 8 + h1i] + adv1;
        lg0 = (lg0 > 0.f) ? lg0 : 0.2f * lg0;
        lg1 = (lg1 > 0.f) ? lg1 : 0.2f * lg1;
        float al0 = __expf(lg0 - m0) * inv0;
        float al1 = __expf(lg1 - m1) * inv1;
        const float* hs = h1 + (size_t)s * 256;
        float4 v0 = *(const float4*)(hs + lane * 4);
        float4 v1 = *(const float4*)(hs + 128 + lane * 4);
        a0.x += al0 * v0.x; a0.y += al0 * v0.y; a0.z += al0 * v0.z; a0.w += al0 * v0.w;
        a1.x += al1 * v1.x; a1.y += al1 * v1.y; a1.z += al1 * v1.z; a1.w += al1 * v1.w;
    }

    // write bf16 split into the dec-GEMM A slot for this hop
    int rb = d >> 7, rloc = d & 127;
    int c0 = lane * 4;
    int kc0 = c0 >> 6, kk0 = c0 & 63;
    uint2 hi0, lo0, hi1, lo1;
    split4(a0, hi0, lo0);
    split4(a1, hi1, lo1);
    size_t sbase = (size_t)hop * SLOT * 2;
    size_t b0 = sbase + ((size_t)rb * 4 + kc0) * 16384 + SMEM_SWZ((uint32_t)(rloc * 128 + kk0 * 2));
    size_t b1 = sbase + ((size_t)rb * 4 + kc0 + 2) * 16384 + SMEM_SWZ((uint32_t)(rloc * 128 + kk0 * 2));
    *(uint2*)((char*)g_gh + b0) = hi0;  *(uint2*)((char*)g_gl + b0) = lo0;
    *(uint2*)((char*)g_gh + b1) = hi1;  *(uint2*)((char*)g_gl + b1) = lo1;
}

// ---------------- layernorm of decay-weighted hop sum + residual ----------------
__global__ void ln_kernel(const float* __restrict__ acc3,
                          const float* __restrict__ scale,
                          const float* __restrict__ bias,
                          const float* __restrict__ res,
                          float* __restrict__ out, int writeSplit)
{
    int gt = blockIdx.x * blockDim.x + threadIdx.x;
    int n = gt >> 5;
    int lane = gt & 31;
    if (n >= Nn) return;
    const float d1 = 0.60653065971263342f, d2 = 0.36787944117144233f;
    const float* a0p = acc3 + (size_t)n * 256;
    const float* a1p = a0p + (size_t)Nn * 256;
    const float* a2p = a1p + (size_t)Nn * 256;
    float4 v0, v1;
    {
        float4 x0 = *(const float4*)(a0p + lane * 4);
        float4 y0 = *(const float4*)(a1p + lane * 4);
        float4 z0 = *(const float4*)(a2p + lane * 4);
        v0.x = x0.x + d1 * y0.x + d2 * z0.x;
        v0.y = x0.y + d1 * y0.y + d2 * z0.y;
        v0.z = x0.z + d1 * y0.z + d2 * z0.z;
        v0.w = x0.w + d1 * y0.w + d2 * z0.w;
        float4 x1 = *(const float4*)(a0p + 128 + lane * 4);
        float4 y1 = *(const float4*)(a1p + 128 + lane * 4);
        float4 z1 = *(const float4*)(a2p + 128 + lane * 4);
        v1.x = x1.x + d1 * y1.x + d2 * z1.x;
        v1.y = x1.y + d1 * y1.y + d2 * z1.y;
        v1.z = x1.z + d1 * y1.z + d2 * z1.z;
        v1.w = x1.w + d1 * y1.w + d2 * z1.w;
    }
    float sm = v0.x + v0.y + v0.z + v0.w + v1.x + v1.y + v1.z + v1.w;
    float sq = v0.x * v0.x + v0.y * v0.y + v0.z * v0.z + v0.w * v0.w
             + v1.x * v1.x + v1.y * v1.y + v1.z * v1.z + v1.w * v1.w;
#pragma unroll
    for (int o = 16; o > 0; o >>= 1) {
        sm += __shfl_xor_sync(0xffffffffu, sm, o);
        sq += __shfl_xor_sync(0xffffffffu, sq, o);
    }
    float mu = sm * (1.f / 256.f);
    float var = sq * (1.f / 256.f) - mu * mu;
    float rstd = rsqrtf(var + 1e-5f);

    const float* rp = res + (size_t)n * 256;
    float4 r0 = *(const float4*)(rp + lane * 4);
    float4 r1 = *(const float4*)(rp + 128 + lane * 4);
    float4 sc0 = *(const float4*)(scale + lane * 4);
    float4 sc1 = *(const float4*)(scale + 128 + lane * 4);
    float4 b0 = *(const float4*)(bias + lane * 4);
    float4 b1 = *(const float4*)(bias + 128 + lane * 4);

    float4 o0, o1;
    o0.x = (v0.x - mu) * rstd * sc0.x + b0.x + r0.x;
    o0.y = (v0.y - mu) * rstd * sc0.y + b0.y + r0.y;
    o0.z = (v0.z - mu) * rstd * sc0.z + b0.z + r0.z;
    o0.w = (v0.w - mu) * rstd * sc0.w + b0.w + r0.w;
    o1.x = (v1.x - mu) * rstd * sc1.x + b1.x + r1.x;
    o1.y = (v1.y - mu) * rstd * sc1.y + b1.y + r1.y;
    o1.z = (v1.z - mu) * rstd * sc1.z + b1.z + r1.z;
    o1.w = (v1.w - mu) * rstd * sc1.w + b1.w + r1.w;

    float* op = out + (size_t)n * 256;
    *(float4*)(op + lane * 4) = o0;
    *(float4*)(op + 128 + lane * 4) = o1;

    if (writeSplit) {
        int rb = n >> 7, rloc = n & 127;
        int c0 = lane * 4;
        int kc0 = c0 >> 6, kk0 = c0 & 63;
        uint2 hi0, lo0, hi1, lo1;
        split4(o0, hi0, lo0);
        split4(o1, hi1, lo1);
        size_t q0 = ((size_t)rb * 4 + kc0) * 16384 + SMEM_SWZ((uint32_t)(rloc * 128 + kk0 * 2));
        size_t q1 = ((size_t)rb * 4 + kc0 + 2) * 16384 + SMEM_SWZ((uint32_t)(rloc * 128 + kk0 * 2));
        *(uint2*)((char*)g_hh + q0) = hi0;  *(uint2*)((char*)g_hl + q0) = lo0;
        *(uint2*)((char*)g_hh + q1) = hi1;  *(uint2*)((char*)g_hl + q1) = lo1;
    }
}

// ---------------- host driver ----------------
extern "C" void kernel_launch(void* const* d_in, const int* in_sizes, int n_in,
                              void* d_out, int out_size)
{
    const float* x        = (const float*)d_in[0];
    const int*   edges    = (const int*)  d_in[1];
    const float* lin1_w   = (const float*)d_in[2];
    const float* lin1_b   = (const float*)d_in[3];
    const float* gat_w    = (const float*)d_in[4];
    const float* att_src  = (const float*)d_in[5];
    const float* att_dst  = (const float*)d_in[6];
    const float* gat_bias = (const float*)d_in[7];
    const float* dec_w    = (const float*)d_in[8];
    const float* dec_b    = (const float*)d_in[9];
    const float* ln_scale = (const float*)d_in[10];
    const float* ln_bias  = (const float*)d_in[11];
    float* out = (float*)d_out;

    cudaFuncSetAttribute(gemm_mma, cudaFuncAttributeMaxDynamicSharedMemorySize, SM_TOTAL);

    float *p_h, *p_h1, *p_acc3, *p_bw;
    __nv_bfloat16 *p_hh, *p_hl, *p_gh, *p_gl;
    int *p_deg;
    cudaGetSymbolAddress((void**)&p_h,    g_h);
    cudaGetSymbolAddress((void**)&p_h1,   g_h1);
    cudaGetSymbolAddress((void**)&p_acc3, g_acc3);
    cudaGetSymbolAddress((void**)&p_bw,   g_bw);
    cudaGetSymbolAddress((void**)&p_hh,   g_hh);
    cudaGetSymbolAddress((void**)&p_hl,   g_hl);
    cudaGetSymbolAddress((void**)&p_gh,   g_gh);
    cudaGetSymbolAddress((void**)&p_gl,   g_gl);
    cudaGetSymbolAddress((void**)&p_deg,  g_deg);

    // preamble
    cudaMemsetAsync(p_deg, 0, 3 * (size_t)Nn * sizeof(int));
    cudaMemcpyAsync(p_bw, dec_b, 6 * 256 * sizeof(float), cudaMemcpyDeviceToDevice);
    convw_kernel<<<(1 * 65536 + 255) / 256, 256>>>(lin1_w, 1, 0);
    convw_kernel<<<(6 * 65536 + 255) / 256, 256>>>(gat_w, 6, 1);
    convw_kernel<<<(6 * 65536 + 255) / 256, 256>>>(dec_w, 6, 7);
    biasw_acc<<<dim3(6, 8), 256>>>(gat_bias, dec_w);
    conva_kernel<<<(Nn * 64 + 255) / 256, 256>>>(x);

    hist3<<<dim3((Ee + 255) / 256, 3), 256>>>(edges);
    bsum3<<<dim3(NB, 3), 256>>>();
    bscan3<<<3, 256>>>();
    rowptr3<<<dim3(NB, 3), 256>>>();
    fill3<<<dim3((Ee + 255) / 256, 3), 256>>>(edges);

    // h = leaky(x @ lin1_w + lin1_b); writes fp32 h + h split
    gemm_mma<<<dim3(NRB, 2), 256, SM_TOTAL>>>(p_gh, p_gl, 0, 0, lin1_b,
                                              nullptr, nullptr, p_h, Nn, 1 | 8, 1.f);

    for (int l = 0; l < 2; l++) {
        // all 3 hop GEMMs: h1[hop] = h @ W[l,hop], fused alphas
        gemm_mma<<<dim3(NRB, 6), 256, SM_TOTAL>>>(p_hh, p_hl, 0, 1 + l * 3, nullptr,
                                                  att_src + (size_t)l * 3 * 256,
                                                  att_dst + (size_t)l * 3 * 256,
                                                  p_h1, Nn, 4, 1.f);
        // fused softmax + aggregate -> g_gh/g_gl per hop
        edge_fused3<<<dim3((Nn * 32 + 255) / 256, 3), 256>>>();

        // all 3 dec GEMMs: acc3[hop] = leaky(agg[hop] @ dec_w + bw), decay in LN
        gemm_mma<<<dim3(NRB, 6), 256, SM_TOTAL>>>(p_gh, p_gl, 1, 7 + l * 3,
                                                  p_bw + l * 3 * 256,
                                                  nullptr, nullptr,
                                                  p_acc3, Nn, 1 | 16, 1.f);

        ln_kernel<<<(Nn * 32 + 255) / 256, 256>>>(
            p_acc3, ln_scale + (size_t)l * 256, ln_bias + (size_t)l * 256,
            p_h, (l == 0) ? p_h : out, (l == 0) ? 1 : 0);
    }
}

// round 13
// speedup vs baseline: 1.0200x; 1.0200x over previous
#include <cuda_runtime.h>
#include <cuda_bf16.h>
#include <cstdint>
#include <cstddef>

#define Nn 50000
#define Ee 300000
#define DH 256
#define NB 196          // ceil(Nn/256)
#define NRB 391         // ceil(Nn/128) row blocks
#define SLOT ((size_t)NRB * 32768)   // bf16 elements per A-split slot

// ================= helpers =================
__device__ __forceinline__ uint32_t smem_to_u32(const void* p) {
    uint32_t a;
    asm("{ .reg .u64 t; cvta.to.shared.u64 t, %1; cvt.u32.u64 %0, t; }" : "=r"(a) : "l"(p));
    return a;
}
__device__ __forceinline__ void ldsm4(uint32_t* r, uint32_t addr) {
    asm volatile("ldmatrix.sync.aligned.m8n8.x4.shared.b16 {%0,%1,%2,%3}, [%4];"
        : "=r"(r[0]), "=r"(r[1]), "=r"(r[2]), "=r"(r[3]) : "r"(addr));
}
__device__ __forceinline__ void ldsm2(uint32_t* r, uint32_t addr) {
    asm volatile("ldmatrix.sync.aligned.m8n8.x2.shared.b16 {%0,%1}, [%2];"
        : "=r"(r[0]), "=r"(r[1]) : "r"(addr));
}
__device__ __forceinline__ void mma16816(float* c, const uint32_t* a, const uint32_t* b) {
    asm volatile("mma.sync.aligned.m16n8k16.row.col.f32.bf16.bf16.f32 "
        "{%0,%1,%2,%3}, {%4,%5,%6,%7}, {%8,%9}, {%0,%1,%2,%3};"
        : "+f"(c[0]), "+f"(c[1]), "+f"(c[2]), "+f"(c[3])
        : "r"(a[0]), "r"(a[1]), "r"(a[2]), "r"(a[3]), "r"(b[0]), "r"(b[1]));
}
#define CP_ASYNC16(sa, gp) \
    asm volatile("cp.async.cg.shared.global [%0], [%1], 16;" :: "r"(sa), "l"(gp))
#define CP_COMMIT() asm volatile("cp.async.commit_group;")
#define CP_WAIT0()  asm volatile("cp.async.wait_group 0;")
#define SMEM_SWZ(o) ((o) ^ ((((uint32_t)(o)) >> 3) & 0x70u))

__device__ __forceinline__ void split4(float4 v, uint2& hi, uint2& lo) {
    __nv_bfloat162 h0, h1, l0, l1;
    h0.x = __float2bfloat16(v.x);  h0.y = __float2bfloat16(v.y);
    h1.x = __float2bfloat16(v.z);  h1.y = __float2bfloat16(v.w);
    l0.x = __float2bfloat16(v.x - __bfloat162float(h0.x));
    l0.y = __float2bfloat16(v.y - __bfloat162float(h0.y));
    l1.x = __float2bfloat16(v.z - __bfloat162float(h1.x));
    l1.y = __float2bfloat16(v.w - __bfloat162float(h1.y));
    hi.x = *(uint32_t*)&h0;  hi.y = *(uint32_t*)&h1;
    lo.x = *(uint32_t*)&l0;  lo.y = *(uint32_t*)&l1;
}

// ================= scratch (static device globals) =================
__device__ float g_h   [(size_t)Nn * DH];        // fp32 h (residual path)
__device__ float g_h1  [3 * (size_t)Nn * DH];    // per-hop GEMM output
__device__ float g_acc3[3 * (size_t)Nn * DH];    // per-hop dec output
__device__ float g_as [3 * (size_t)Nn * 8];
__device__ float g_ad [3 * (size_t)Nn * 8];
__device__ float g_s  [3 * (size_t)Nn * 8];
__device__ float g_e  [3 * (size_t)Ee * 8];
__device__ float g_bw [6 * 256];                 // folded dec column bias
// weights: 13 matrices, [4 kc][256 n][64 k] bf16 swizzled
__device__ __nv_bfloat16 g_bh[13 * 65536];
__device__ __nv_bfloat16 g_bl[13 * 65536];
// A splits: h (1 slot) + x/agg (3 slots, per hop)
__device__ __nv_bfloat16 g_hh[SLOT];
__device__ __nv_bfloat16 g_hl[SLOT];
__device__ __nv_bfloat16 g_gh[3 * SLOT];
__device__ __nv_bfloat16 g_gl[3 * SLOT];
// CSR (by dst)
__device__ int g_deg [3][Nn];
__device__ int g_rp  [3][Nn];
__device__ int g_csrc[3][Ee];
__device__ int g_cur [3][Nn];
__device__ int g_bsum[3][256];

// ---------------- weight convert ----------------
__global__ void convw_kernel(const float* __restrict__ W, int nmat, int gbase)
{
    int id = blockIdx.x * blockDim.x + threadIdx.x;
    if (id >= nmat * 65536) return;
    int g = id >> 16;
    int r = id & 65535;
    int n = r & 255;
    int kf = r >> 8;
    float v = W[(size_t)g * 65536 + (size_t)kf * 256 + n];
    __nv_bfloat16 hi = __float2bfloat16(v);
    __nv_bfloat16 lo = __float2bfloat16(v - __bfloat162float(hi));
    int kc = kf >> 6, kk = kf & 63;
    uint32_t off = (uint32_t)kc * 32768u + SMEM_SWZ((uint32_t)(n * 128 + kk * 2));
    size_t base = (size_t)(gbase + g) * 131072u;
    *(__nv_bfloat16*)((char*)g_bh + base + off) = hi;
    *(__nv_bfloat16*)((char*)g_bl + base + off) = lo;
}

// ---------------- x split into slot 0 of g_gh/g_gl ----------------
__global__ void conva_kernel(const float* __restrict__ A)
{
    int id = blockIdx.x * blockDim.x + threadIdx.x;
    if (id >= Nn * 64) return;
    int r = id >> 6, q = id & 63;
    float4 v = *(const float4*)(A + (size_t)r * 256 + q * 4);
    uint2 hi, lo;
    split4(v, hi, lo);
    int rb = r >> 7, rloc = r & 127;
    int kc = q >> 4, kk = (q & 15) * 4;
    size_t off = ((size_t)rb * 4 + kc) * 16384 + SMEM_SWZ((uint32_t)(rloc * 128 + kk * 2));
    *(uint2*)((char*)g_gh + off) = hi;
    *(uint2*)((char*)g_gl + off) = lo;
}

// ---------------- folded dec bias accumulate: g_bw += gat_bias @ dec_w ----------
__global__ void biasw_acc(const float* __restrict__ gat_bias,
                          const float* __restrict__ dec_w)
{
    int lk = blockIdx.x;
    int n = threadIdx.x;
    int k0 = blockIdx.y * 32;
    const float* W = dec_w + (size_t)lk * 65536;
    const float* gb = gat_bias + lk * 256;
    float acc = 0.f;
#pragma unroll
    for (int k = 0; k < 32; k++) acc += gb[k0 + k] * W[(k0 + k) * 256 + n];
    atomicAdd(&g_bw[lk * 256 + n], acc);
}

// ---------------- CSR build (all 3 hops batched via blockIdx.y) ----------------
__global__ void hist3(const int* __restrict__ edges)
{
    int hop = blockIdx.y;
    int e = blockIdx.x * blockDim.x + threadIdx.x;
    if (e < Ee) atomicAdd(&g_deg[hop][edges[(size_t)hop * 2 * Ee + Ee + e]], 1);
}
__global__ void bsum3()
{
    __shared__ int ws[8];
    int hop = blockIdx.y;
    int i = blockIdx.x * 256 + threadIdx.x;
    int v = (i < Nn) ? g_deg[hop][i] : 0;
#pragma unroll
    for (int o = 16; o > 0; o >>= 1) v += __shfl_xor_sync(0xffffffffu, v, o);
    if ((threadIdx.x & 31) == 0) ws[threadIdx.x >> 5] = v;
    __syncthreads();
    if (threadIdx.x < 8) {
        int x = ws[threadIdx.x];
#pragma unroll
        for (int o = 4; o > 0; o >>= 1) x += __shfl_xor_sync(0xffu, x, o);
        if (threadIdx.x == 0) g_bsum[hop][blockIdx.x] = x;
    }
}
__global__ void bscan3()   // grid 3: exclusive scan per hop
{
    __shared__ int sh[256];
    int hop = blockIdx.x;
    int t = threadIdx.x;
    int orig = (t < NB) ? g_bsum[hop][t] : 0;
    sh[t] = orig;
    __syncthreads();
#pragma unroll
    for (int o = 1; o < 256; o <<= 1) {
        int v = (t >= o) ? sh[t - o] : 0;
        __syncthreads();
        sh[t] += v;
        __syncthreads();
    }
    if (t < NB) g_bsum[hop][t] = sh[t] - orig;
}
__global__ void rowptr3()
{
    __shared__ int sh[256];
    int hop = blockIdx.y;
    int t = threadIdx.x;
    int i = blockIdx.x * 256 + t;
    int d = (i < Nn) ? g_deg[hop][i] : 0;
    sh[t] = d;
    __syncthreads();
#pragma unroll
    for (int o = 1; o < 256; o <<= 1) {
        int v = (t >= o) ? sh[t - o] : 0;
        __syncthreads();
        sh[t] += v;
        __syncthreads();
    }
    if (i < Nn) {
        int rp = g_bsum[hop][blockIdx.x] + sh[t] - d;
        g_rp[hop][i] = rp;
        g_cur[hop][i] = rp;
    }
}
__global__ void fill3(const int* __restrict__ edges)
{
    int hop = blockIdx.y;
    int e = blockIdx.x * blockDim.x + threadIdx.x;
    if (e >= Ee) return;
    const int* src = edges + (size_t)hop * 2 * Ee;
    const int* dst = src + Ee;
    int pos = atomicAdd(&g_cur[hop][dst[e]], 1);
    g_csrc[hop][pos] = src[e];
}

// ---------------- GEMM (multi-hop via blockIdx.y; B double-buffered) ----------
// grid (NRB, 2*nhop): hop = blockIdx.y>>1, colBase = (blockIdx.y&1)*128
// mode bit0: leaky(0.01); bit2: emit alphas; bit3: write h split;
// bit4: per-hop bbias (bbias += hop*256); A slot per hop when aHop!=0
#define SM_AH 0
#define SM_AL 16384
#define SM_B0 32768
#define SM_B1 65536
#define SM_TOTAL 98304

__global__ void __launch_bounds__(256, 2) gemm_mma(
    const __nv_bfloat16* __restrict__ Ah, const __nv_bfloat16* __restrict__ Al,
    int aHop, int gidxBase, const float* __restrict__ bbias,
    const float* __restrict__ attS, const float* __restrict__ attD,
    float* __restrict__ C, int M, int mode, float scale)
{
    extern __shared__ char smem[];
    const uint32_t sb = smem_to_u32(smem);
    const int tid = threadIdx.x, wid = tid >> 5, lane = tid & 31;
    const int hop = blockIdx.y >> 1;
    const int rowBase = blockIdx.x * 128;
    const int colBase = (blockIdx.y & 1) * 128;
    const int warpM = (wid & 1) * 64;
    const int warpN = (wid >> 1) * 32;

    const char* bh = (const char*)g_bh + (size_t)(gidxBase + hop) * 131072u + (size_t)colBase * 128u;
    const char* bl = (const char*)g_bl + (size_t)(gidxBase + hop) * 131072u + (size_t)colBase * 128u;
    const size_t aoff = (size_t)blockIdx.x * 65536u + (aHop ? (size_t)hop * (SLOT * 2) : 0);
    const char* ah = (const char*)Ah + aoff;
    const char* al = (const char*)Al + aoff;
    C += (size_t)hop * Nn * 256;
    if (mode & 16) bbias += hop * 256;

    float acc[4][4][4];
#pragma unroll
    for (int i = 0; i < 4; i++)
#pragma unroll
        for (int j = 0; j < 4; j++)
#pragma unroll
            for (int c = 0; c < 4; c++) acc[i][j][c] = 0.f;

    const uint32_t xorA = (uint32_t)((lane & 7) << 4);
    const uint32_t aRow = (uint32_t)(warpM + (lane & 15));
    const uint32_t aSel = (uint32_t)((lane >> 4) << 4);
    const uint32_t bRow = (uint32_t)(warpN + (lane & 7));
    const uint32_t bSel = (uint32_t)(((lane >> 3) & 1) << 4);

    // ---- copy helpers ----
    auto cpA = [&](int kc) {
        const char* sah = ah + (size_t)kc * 16384;
        const char* sal = al + (size_t)kc * 16384;
#pragma unroll
        for (int it = 0; it < 4; it++) {
            uint32_t j = (uint32_t)(tid + it * 256) * 16u;
            CP_ASYNC16(sb + SM_AH + j, sah + j);
            CP_ASYNC16(sb + SM_AL + j, sal + j);
        }
    };
    auto cpB = [&](int kc, uint32_t bbase) {
        const char* sbh = bh + (size_t)kc * 32768;
        const char* sbl = bl + (size_t)kc * 32768;
#pragma unroll
        for (int it = 0; it < 4; it++) {     // 16KB BH + 16KB BL per buffer
            uint32_t j = (uint32_t)(tid + it * 256) * 16u;
            CP_ASYNC16(sb + bbase + j, sbh + j);
            CP_ASYNC16(sb + bbase + 16384 + j, sbl + j);
        }
    };

    // ---- prologue: A(0) + B(0) ----
    cpA(0);
    cpB(0, SM_B0);
    CP_COMMIT();
    CP_WAIT0();
    __syncthreads();

    for (int kc = 0; kc < 4; kc++) {
        const uint32_t bbase = (kc & 1) ? SM_B1 : SM_B0;
        if (kc < 3) {
            cpB(kc + 1, bbase ^ (SM_B0 ^ SM_B1));
            CP_COMMIT();
        }
#pragma unroll
        for (int ks = 0; ks < 4; ks++) {
            uint32_t ahf[4][4], alf[4][4], bhf[4][2], blf[4][2];
            const uint32_t kOffA = (uint32_t)(ks * 32) + aSel;
            const uint32_t kOffB = (uint32_t)(ks * 32) + bSel;
#pragma unroll
            for (int i = 0; i < 4; i++) {
                uint32_t off = (((aRow + i * 16) * 128u + kOffA) ^ xorA);
                ldsm4(ahf[i], sb + SM_AH + off);
                ldsm4(alf[i], sb + SM_AL + off);
            }
#pragma unroll
            for (int j = 0; j < 4; j++) {
                uint32_t off = (((bRow + j * 8) * 128u + kOffB) ^ xorA);
                ldsm2(bhf[j], sb + bbase + off);
                ldsm2(blf[j], sb + bbase + 16384 + off);
            }
#pragma unroll
            for (int i = 0; i < 4; i++)
#pragma unroll
                for (int j = 0; j < 4; j++) mma16816(acc[i][j], ahf[i], bhf[j]);
#pragma unroll
            for (int i = 0; i < 4; i++)
#pragma unroll
                for (int j = 0; j < 4; j++) mma16816(acc[i][j], ahf[i], blf[j]);
#pragma unroll
            for (int i = 0; i < 4; i++)
#pragma unroll
                for (int j = 0; j < 4; j++) mma16816(acc[i][j], alf[i], bhf[j]);
        }
        if (kc < 3) {
            __syncthreads();       // all MMA(kc) reads of A buffer done
            cpA(kc + 1);
            CP_COMMIT();
            CP_WAIT0();
            __syncthreads();
        }
    }

    // ---- epilogue ----
    const int tg = lane >> 2;
    const int tc = (lane & 3) * 2;
    const int head = (blockIdx.y & 1) * 4 + (wid >> 1);
#pragma unroll
    for (int i = 0; i < 4; i++) {
        int rloc = warpM + i * 16 + tg;
        int r0 = rowBase + rloc;
        float as0 = 0.f, ad0 = 0.f, as1 = 0.f, ad1 = 0.f;
#pragma unroll
        for (int j = 0; j < 4; j++) {
            int col = colBase + warpN + j * 8 + tc;
            float b0 = bbias ? bbias[col] : 0.f;
            float b1 = bbias ? bbias[col + 1] : 0.f;
            float v0 = acc[i][j][0] + b0, v1 = acc[i][j][1] + b1;
            float v2 = acc[i][j][2] + b0, v3 = acc[i][j][3] + b1;
            if (mode & 1) {
                v0 = (v0 > 0.f) ? v0 : 0.01f * v0;
                v1 = (v1 > 0.f) ? v1 : 0.01f * v1;
                v2 = (v2 > 0.f) ? v2 : 0.01f * v2;
                v3 = (v3 > 0.f) ? v3 : 0.01f * v3;
            }
            v0 *= scale; v1 *= scale; v2 *= scale; v3 *= scale;
            if (r0 < M)
                *(float2*)(C + (size_t)r0 * 256 + col) = make_float2(v0, v1);
            if (r0 + 8 < M)
                *(float2*)(C + (size_t)(r0 + 8) * 256 + col) = make_float2(v2, v3);
            if (mode & 8) {
                int kcq = col >> 6, kk = col & 63;
                size_t tb = ((size_t)blockIdx.x * 4 + kcq) * 16384;
                if (r0 < M) {
                    uint32_t so = SMEM_SWZ((uint32_t)(rloc * 128 + kk * 2));
                    __nv_bfloat162 hp, lp;
                    hp.x = __float2bfloat16(v0); hp.y = __float2bfloat16(v1);
                    lp.x = __float2bfloat16(v0 - __bfloat162float(hp.x));
                    lp.y = __float2bfloat16(v1 - __bfloat162float(hp.y));
                    *(uint32_t*)((char*)g_hh + tb + so) = *(uint32_t*)&hp;
                    *(uint32_t*)((char*)g_hl + tb + so) = *(uint32_t*)&lp;
                }
                if (r0 + 8 < M) {
                    uint32_t so = SMEM_SWZ((uint32_t)((rloc + 8) * 128 + kk * 2));
                    __nv_bfloat162 hp, lp;
                    hp.x = __float2bfloat16(v2); hp.y = __float2bfloat16(v3);
                    lp.x = __float2bfloat16(v2 - __bfloat162float(hp.x));
                    lp.y = __float2bfloat16(v3 - __bfloat162float(hp.y));
                    *(uint32_t*)((char*)g_hh + tb + so) = *(uint32_t*)&hp;
                    *(uint32_t*)((char*)g_hl + tb + so) = *(uint32_t*)&lp;
                }
            }
            if (mode & 4) {
                float s0 = attS[hop * 256 + col], s1 = attS[hop * 256 + col + 1];
                float d0 = attD[hop * 256 + col], d1 = attD[hop * 256 + col + 1];
                as0 += v0 * s0 + v1 * s1;  ad0 += v0 * d0 + v1 * d1;
                as1 += v2 * s0 + v3 * s1;  ad1 += v2 * d0 + v3 * d1;
            }
        }
        if (mode & 4) {
#pragma unroll
            for (int o = 1; o <= 2; o <<= 1) {
                as0 += __shfl_xor_sync(0xffffffffu, as0, o);
                ad0 += __shfl_xor_sync(0xffffffffu, ad0, o);
                as1 += __shfl_xor_sync(0xffffffffu, as1, o);
                ad1 += __shfl_xor_sync(0xffffffffu, ad1, o);
            }
            if ((lane & 3) == 0) {
                size_t ab = (size_t)hop * Nn * 8;
                if (r0 < M)     { g_as[ab + (size_t)r0 * 8 + head] = as0;       g_ad[ab + (size_t)r0 * 8 + head] = ad0; }
                if (r0 + 8 < M) { g_as[ab + (size_t)(r0 + 8) * 8 + head] = as1; g_ad[ab + (size_t)(r0 + 8) * 8 + head] = ad1; }
            }
        }
    }
}

// ---------------- attention softmax (3 hops batched) ----------------
__global__ void attn_csr3()
{
    int t = blockIdx.x * blockDim.x + threadIdx.x;
    if (t >= Nn * 8) return;
    int hop = blockIdx.y;
    int d = t >> 3, h = t & 7;
    int start = g_rp[hop][d];
    int end = start + g_deg[hop][d];
    const float* as = g_as + (size_t)hop * Nn * 8;
    float* ge = g_e + (size_t)hop * Ee * 8;
    float adv = g_ad[(size_t)hop * Nn * 8 + (size_t)d * 8 + h];
    float m = -3.4e38f;
    for (int j = start; j < end; j++) {
        int s = g_csrc[hop][j];
        float lg = as[(size_t)s * 8 + h] + adv;
        lg = (lg > 0.f) ? lg : 0.2f * lg;
        ge[(size_t)j * 8 + h] = lg;
        m = fmaxf(m, lg);
    }
    float sum = 0.f;
    for (int j = start; j < end; j++) {
        float v = __expf(ge[(size_t)j * 8 + h] - m);
        ge[(size_t)j * 8 + h] = v;
        sum += v;
    }
    g_s[(size_t)hop * Nn * 8 + (size_t)d * 8 + h] = sum;
}

// ---------------- aggregate (3 hops batched); writes agg bf16 split -------------
__global__ void edge3_csr3()
{
    int gt = blockIdx.x * blockDim.x + threadIdx.x;
    int d = gt >> 5, lane = gt & 31;
    if (d >= Nn) return;
    int hop = blockIdx.y;
    int start = g_rp[hop][d];
    int end = start + g_deg[hop][d];
    const float* ge = g_e + (size_t)hop * Ee * 8;
    const float* h1 = g_h1 + (size_t)hop * Nn * 256;
    int h0 = lane >> 3, h1i = 4 + (lane >> 3);
    float i0 = 1.f / (g_s[(size_t)hop * Nn * 8 + (size_t)d * 8 + h0] + 1e-16f);
    float i1 = 1.f / (g_s[(size_t)hop * Nn * 8 + (size_t)d * 8 + h1i] + 1e-16f);
    float4 a0 = make_float4(0.f, 0.f, 0.f, 0.f);
    float4 a1 = a0;
    for (int j = start; j < end; j++) {
        int s = g_csrc[hop][j];
        float al0 = ge[(size_t)j * 8 + h0] * i0;
        float al1 = ge[(size_t)j * 8 + h1i] * i1;
        const float* hs = h1 + (size_t)s * 256;
        float4 v0 = *(const float4*)(hs + lane * 4);
        float4 v1 = *(const float4*)(hs + 128 + lane * 4);
        a0.x += al0 * v0.x; a0.y += al0 * v0.y; a0.z += al0 * v0.z; a0.w += al0 * v0.w;
        a1.x += al1 * v1.x; a1.y += al1 * v1.y; a1.z += al1 * v1.z; a1.w += al1 * v1.w;
    }
    int rb = d >> 7, rloc = d & 127;
    int c0 = lane * 4;
    int kc0 = c0 >> 6, kk0 = c0 & 63;
    uint2 hi0, lo0, hi1, lo1;
    split4(a0, hi0, lo0);
    split4(a1, hi1, lo1);
    size_t sbase = (size_t)hop * SLOT * 2;
    size_t b0 = sbase + ((size_t)rb * 4 + kc0) * 16384 + SMEM_SWZ((uint32_t)(rloc * 128 + kk0 * 2));
    size_t b1 = sbase + ((size_t)rb * 4 + kc0 + 2) * 16384 + SMEM_SWZ((uint32_t)(rloc * 128 + kk0 * 2));
    *(uint2*)((char*)g_gh + b0) = hi0;  *(uint2*)((char*)g_gl + b0) = lo0;
    *(uint2*)((char*)g_gh + b1) = hi1;  *(uint2*)((char*)g_gl + b1) = lo1;
}

// ---------------- layernorm of decay-weighted hop sum + residual ----------------
__global__ void ln_kernel(const float* __restrict__ acc3,
                          const float* __restrict__ scale,
                          const float* __restrict__ bias,
                          const float* __restrict__ res,
                          float* __restrict__ out, int writeSplit)
{
    int gt = blockIdx.x * blockDim.x + threadIdx.x;
    int n = gt >> 5;
    int lane = gt & 31;
    if (n >= Nn) return;
    const float d1 = 0.60653065971263342f, d2 = 0.36787944117144233f;
    const float* a0p = acc3 + (size_t)n * 256;
    const float* a1p = a0p + (size_t)Nn * 256;
    const float* a2p = a1p + (size_t)Nn * 256;
    float4 v0, v1;
    {
        float4 x0 = *(const float4*)(a0p + lane * 4);
        float4 y0 = *(const float4*)(a1p + lane * 4);
        float4 z0 = *(const float4*)(a2p + lane * 4);
        v0.x = x0.x + d1 * y0.x + d2 * z0.x;
        v0.y = x0.y + d1 * y0.y + d2 * z0.y;
        v0.z = x0.z + d1 * y0.z + d2 * z0.z;
        v0.w = x0.w + d1 * y0.w + d2 * z0.w;
        float4 x1 = *(const float4*)(a0p + 128 + lane * 4);
        float4 y1 = *(const float4*)(a1p + 128 + lane * 4);
        float4 z1 = *(const float4*)(a2p + 128 + lane * 4);
        v1.x = x1.x + d1 * y1.x + d2 * z1.x;
        v1.y = x1.y + d1 * y1.y + d2 * z1.y;
        v1.z = x1.z + d1 * y1.z + d2 * z1.z;
        v1.w = x1.w + d1 * y1.w + d2 * z1.w;
    }
    float sm = v0.x + v0.y + v0.z + v0.w + v1.x + v1.y + v1.z + v1.w;
    float sq = v0.x * v0.x + v0.y * v0.y + v0.z * v0.z + v0.w * v0.w
             + v1.x * v1.x + v1.y * v1.y + v1.z * v1.z + v1.w * v1.w;
#pragma unroll
    for (int o = 16; o > 0; o >>= 1) {
        sm += __shfl_xor_sync(0xffffffffu, sm, o);
        sq += __shfl_xor_sync(0xffffffffu, sq, o);
    }
    float mu = sm * (1.f / 256.f);
    float var = sq * (1.f / 256.f) - mu * mu;
    float rstd = rsqrtf(var + 1e-5f);

    const float* rp = res + (size_t)n * 256;
    float4 r0 = *(const float4*)(rp + lane * 4);
    float4 r1 = *(const float4*)(rp + 128 + lane * 4);
    float4 sc0 = *(const float4*)(scale + lane * 4);
    float4 sc1 = *(const float4*)(scale + 128 + lane * 4);
    float4 b0 = *(const float4*)(bias + lane * 4);
    float4 b1 = *(const float4*)(bias + 128 + lane * 4);

    float4 o0, o1;
    o0.x = (v0.x - mu) * rstd * sc0.x + b0.x + r0.x;
    o0.y = (v0.y - mu) * rstd * sc0.y + b0.y + r0.y;
    o0.z = (v0.z - mu) * rstd * sc0.z + b0.z + r0.z;
    o0.w = (v0.w - mu) * rstd * sc0.w + b0.w + r0.w;
    o1.x = (v1.x - mu) * rstd * sc1.x + b1.x + r1.x;
    o1.y = (v1.y - mu) * rstd * sc1.y + b1.y + r1.y;
    o1.z = (v1.z - mu) * rstd * sc1.z + b1.z + r1.z;
    o1.w = (v1.w - mu) * rstd * sc1.w + b1.w + r1.w;

    float* op = out + (size_t)n * 256;
    *(float4*)(op + lane * 4) = o0;
    *(float4*)(op + 128 + lane * 4) = o1;

    if (writeSplit) {
        int rb = n >> 7, rloc = n & 127;
        int c0 = lane * 4;
        int kc0 = c0 >> 6, kk0 = c0 & 63;
        uint2 hi0, lo0, hi1, lo1;
        split4(o0, hi0, lo0);
        split4(o1, hi1, lo1);
        size_t q0 = ((size_t)rb * 4 + kc0) * 16384 + SMEM_SWZ((uint32_t)(rloc * 128 + kk0 * 2));
        size_t q1 = ((size_t)rb * 4 + kc0 + 2) * 16384 + SMEM_SWZ((uint32_t)(rloc * 128 + kk0 * 2));
        *(uint2*)((char*)g_hh + q0) = hi0;  *(uint2*)((char*)g_hl + q0) = lo0;
        *(uint2*)((char*)g_hh + q1) = hi1;  *(uint2*)((char*)g_hl + q1) = lo1;
    }
}

// ---------------- host driver ----------------
extern "C" void kernel_launch(void* const* d_in, const int* in_sizes, int n_in,
                              void* d_out, int out_size)
{
    const float* x        = (const float*)d_in[0];
    const int*   edges    = (const int*)  d_in[1];
    const float* lin1_w   = (const float*)d_in[2];
    const float* lin1_b   = (const float*)d_in[3];
    const float* gat_w    = (const float*)d_in[4];
    const float* att_src  = (const float*)d_in[5];
    const float* att_dst  = (const float*)d_in[6];
    const float* gat_bias = (const float*)d_in[7];
    const float* dec_w    = (const float*)d_in[8];
    const float* dec_b    = (const float*)d_in[9];
    const float* ln_scale = (const float*)d_in[10];
    const float* ln_bias  = (const float*)d_in[11];
    float* out = (float*)d_out;

    cudaFuncSetAttribute(gemm_mma, cudaFuncAttributeMaxDynamicSharedMemorySize, SM_TOTAL);

    float *p_h, *p_h1, *p_acc3, *p_bw;
    __nv_bfloat16 *p_hh, *p_hl, *p_gh, *p_gl;
    int *p_deg;
    cudaGetSymbolAddress((void**)&p_h,    g_h);
    cudaGetSymbolAddress((void**)&p_h1,   g_h1);
    cudaGetSymbolAddress((void**)&p_acc3, g_acc3);
    cudaGetSymbolAddress((void**)&p_bw,   g_bw);
    cudaGetSymbolAddress((void**)&p_hh,   g_hh);
    cudaGetSymbolAddress((void**)&p_hl,   g_hl);
    cudaGetSymbolAddress((void**)&p_gh,   g_gh);
    cudaGetSymbolAddress((void**)&p_gl,   g_gl);
    cudaGetSymbolAddress((void**)&p_deg,  g_deg);

    // preamble
    cudaMemsetAsync(p_deg, 0, 3 * (size_t)Nn * sizeof(int));
    cudaMemcpyAsync(p_bw, dec_b, 6 * 256 * sizeof(float), cudaMemcpyDeviceToDevice);
    convw_kernel<<<(1 * 65536 + 255) / 256, 256>>>(lin1_w, 1, 0);
    convw_kernel<<<(6 * 65536 + 255) / 256, 256>>>(gat_w, 6, 1);
    convw_kernel<<<(6 * 65536 + 255) / 256, 256>>>(dec_w, 6, 7);
    biasw_acc<<<dim3(6, 8), 256>>>(gat_bias, dec_w);
    conva_kernel<<<(Nn * 64 + 255) / 256, 256>>>(x);

    hist3<<<dim3((Ee + 255) / 256, 3), 256>>>(edges);
    bsum3<<<dim3(NB, 3), 256>>>();
    bscan3<<<3, 256>>>();
    rowptr3<<<dim3(NB, 3), 256>>>();
    fill3<<<dim3((Ee + 255) / 256, 3), 256>>>(edges);

    // h = leaky(x @ lin1_w + lin1_b); writes fp32 h + h split
    gemm_mma<<<dim3(NRB, 2), 256, SM_TOTAL>>>(p_gh, p_gl, 0, 0, lin1_b,
                                              nullptr, nullptr, p_h, Nn, 1 | 8, 1.f);

    for (int l = 0; l < 2; l++) {
        // all 3 hop GEMMs: h1[hop] = h @ W[l,hop], fused alphas
        gemm_mma<<<dim3(NRB, 6), 256, SM_TOTAL>>>(p_hh, p_hl, 0, 1 + l * 3, nullptr,
                                                  att_src + (size_t)l * 3 * 256,
                                                  att_dst + (size_t)l * 3 * 256,
                                                  p_h1, Nn, 4, 1.f);
        attn_csr3<<<dim3((Nn * 8 + 255) / 256, 3), 256>>>();
        edge3_csr3<<<dim3((Nn * 32 + 255) / 256, 3), 256>>>();

        // all 3 dec GEMMs: acc3[hop] = leaky(agg[hop] @ dec_w + bw), decay in LN
        gemm_mma<<<dim3(NRB, 6), 256, SM_TOTAL>>>(p_gh, p_gl, 1, 7 + l * 3,
                                                  p_bw + l * 3 * 256,
                                                  nullptr, nullptr,
                                                  p_acc3, Nn, 1 | 16, 1.f);

        ln_kernel<<<(Nn * 32 + 255) / 256, 256>>>(
            p_acc3, ln_scale + (size_t)l * 256, ln_bias + (size_t)l * 256,
            p_h, (l == 0) ? p_h : out, (l == 0) ? 1 : 0);
    }
}

// round 14
// speedup vs baseline: 1.0287x; 1.0086x over previous
#include <cuda_runtime.h>
#include <cuda_bf16.h>
#include <cstdint>
#include <cstddef>

#define Nn 50000
#define Ee 300000
#define DH 256
#define NB 196          // ceil(Nn/256)
#define NRB 391         // ceil(Nn/128) row blocks
#define SLOT ((size_t)NRB * 32768)   // bf16 elements per A-split slot

// prep_kernel block ranges
#define B_CONVW 3328    // 13*65536/256
#define B_CONVA 12500   // Nn*64/256
#define B_HISTH 1172    // ceil(Ee/256)
#define B_HIST  (3 * B_HISTH)
#define B_BIASW 48      // 6 lk * 8 kslices
#define B_PREP  (B_CONVW + B_CONVA + B_HIST + B_BIASW)

// ================= helpers =================
__device__ __forceinline__ uint32_t smem_to_u32(const void* p) {
    uint32_t a;
    asm("{ .reg .u64 t; cvta.to.shared.u64 t, %1; cvt.u32.u64 %0, t; }" : "=r"(a) : "l"(p));
    return a;
}
__device__ __forceinline__ void ldsm4(uint32_t* r, uint32_t addr) {
    asm volatile("ldmatrix.sync.aligned.m8n8.x4.shared.b16 {%0,%1,%2,%3}, [%4];"
        : "=r"(r[0]), "=r"(r[1]), "=r"(r[2]), "=r"(r[3]) : "r"(addr));
}
__device__ __forceinline__ void mma16816(float* c, const uint32_t* a, const uint32_t* b) {
    asm volatile("mma.sync.aligned.m16n8k16.row.col.f32.bf16.bf16.f32 "
        "{%0,%1,%2,%3}, {%4,%5,%6,%7}, {%8,%9}, {%0,%1,%2,%3};"
        : "+f"(c[0]), "+f"(c[1]), "+f"(c[2]), "+f"(c[3])
        : "r"(a[0]), "r"(a[1]), "r"(a[2]), "r"(a[3]), "r"(b[0]), "r"(b[1]));
}
#define CP_ASYNC16(sa, gp) \
    asm volatile("cp.async.cg.shared.global [%0], [%1], 16;" :: "r"(sa), "l"(gp))
#define CP_COMMIT() asm volatile("cp.async.commit_group;")
#define CP_WAIT0()  asm volatile("cp.async.wait_group 0;")
#define SMEM_SWZ(o) ((o) ^ ((((uint32_t)(o)) >> 3) & 0x70u))

__device__ __forceinline__ void split4(float4 v, uint2& hi, uint2& lo) {
    __nv_bfloat162 h0, h1, l0, l1;
    h0.x = __float2bfloat16(v.x);  h0.y = __float2bfloat16(v.y);
    h1.x = __float2bfloat16(v.z);  h1.y = __float2bfloat16(v.w);
    l0.x = __float2bfloat16(v.x - __bfloat162float(h0.x));
    l0.y = __float2bfloat16(v.y - __bfloat162float(h0.y));
    l1.x = __float2bfloat16(v.z - __bfloat162float(h1.x));
    l1.y = __float2bfloat16(v.w - __bfloat162float(h1.y));
    hi.x = *(uint32_t*)&h0;  hi.y = *(uint32_t*)&h1;
    lo.x = *(uint32_t*)&l0;  lo.y = *(uint32_t*)&l1;
}

// ================= scratch (static device globals) =================
__device__ float g_h   [(size_t)Nn * DH];        // fp32 h (residual path)
__device__ float g_h1  [3 * (size_t)Nn * DH];    // per-hop GEMM output
__device__ float g_acc3[3 * (size_t)Nn * DH];    // per-hop dec output
__device__ float g_as [3 * (size_t)Nn * 8];
__device__ float g_ad [3 * (size_t)Nn * 8];
__device__ float g_s  [3 * (size_t)Nn * 8];
__device__ float g_e  [3 * (size_t)Ee * 8];
__device__ float g_bw [6 * 256];                 // folded dec column bias
// weights: 13 matrices, [4 kc][256 n][64 k] bf16 swizzled
__device__ __nv_bfloat16 g_bh[13 * 65536];
__device__ __nv_bfloat16 g_bl[13 * 65536];
// A splits: h (1 slot) + x/agg (3 slots, per hop)
__device__ __nv_bfloat16 g_hh[SLOT];
__device__ __nv_bfloat16 g_hl[SLOT];
__device__ __nv_bfloat16 g_gh[3 * SLOT];
__device__ __nv_bfloat16 g_gl[3 * SLOT];
// CSR (by dst)
__device__ int g_deg [3][Nn];
__device__ int g_rp  [3][Nn];
__device__ int g_csrc[3][Ee];
__device__ int g_cur [3][Nn];
__device__ int g_bsum[3][256];

// ---------------- prep: convw(13) + conva + hist3 + biasw, one launch ----------
__global__ void prep_kernel(const float* __restrict__ lin1_w,
                            const float* __restrict__ gat_w,
                            const float* __restrict__ dec_w,
                            const float* __restrict__ x,
                            const float* __restrict__ gat_bias,
                            const int* __restrict__ edges)
{
    int b = blockIdx.x;
    int tid = threadIdx.x;
    if (b < B_CONVW) {
        // weight convert: W[k][n] -> swizzled bf16 hi/lo
        int id = b * 256 + tid;
        int g = id >> 16;
        int r = id & 65535;
        int n = r & 255;
        int kf = r >> 8;
        const float* W = (g == 0) ? (lin1_w + r)
                       : (g < 7)  ? (gat_w + (size_t)(g - 1) * 65536 + r)
                                  : (dec_w + (size_t)(g - 7) * 65536 + r);
        float v = *W;
        __nv_bfloat16 hi = __float2bfloat16(v);
        __nv_bfloat16 lo = __float2bfloat16(v - __bfloat162float(hi));
        int kc = kf >> 6, kk = kf & 63;
        uint32_t off = (uint32_t)kc * 32768u + SMEM_SWZ((uint32_t)(n * 128 + kk * 2));
        size_t base = (size_t)g * 131072u;
        *(__nv_bfloat16*)((char*)g_bh + base + off) = hi;
        *(__nv_bfloat16*)((char*)g_bl + base + off) = lo;
        return;
    }
    b -= B_CONVW;
    if (b < B_CONVA) {
        // x split into slot 0 of g_gh/g_gl
        int id = b * 256 + tid;
        int r = id >> 6, q = id & 63;
        float4 v = *(const float4*)(x + (size_t)r * 256 + q * 4);
        uint2 hi, lo;
        split4(v, hi, lo);
        int rb = r >> 7, rloc = r & 127;
        int kc = q >> 4, kk = (q & 15) * 4;
        size_t off = ((size_t)rb * 4 + kc) * 16384 + SMEM_SWZ((uint32_t)(rloc * 128 + kk * 2));
        *(uint2*)((char*)g_gh + off) = hi;
        *(uint2*)((char*)g_gl + off) = lo;
        return;
    }
    b -= B_CONVA;
    if (b < B_HIST) {
        int hop = b / B_HISTH;
        int e = (b - hop * B_HISTH) * 256 + tid;
        if (e < Ee) atomicAdd(&g_deg[hop][edges[(size_t)hop * 2 * Ee + Ee + e]], 1);
        return;
    }
    b -= B_HIST;
    {
        // biasw: g_bw += gat_bias @ dec_w  (g_bw pre-initialized with dec_b)
        int lk = b >> 3;
        int k0 = (b & 7) * 32;
        const float* W = dec_w + (size_t)lk * 65536;
        const float* gb = gat_bias + lk * 256;
        float acc = 0.f;
#pragma unroll
        for (int k = 0; k < 32; k++) acc += gb[k0 + k] * W[(k0 + k) * 256 + tid];
        atomicAdd(&g_bw[lk * 256 + tid], acc);
    }
}

// ---------------- CSR scan chain ----------------
__global__ void bsum3()
{
    __shared__ int ws[8];
    int hop = blockIdx.y;
    int i = blockIdx.x * 256 + threadIdx.x;
    int v = (i < Nn) ? g_deg[hop][i] : 0;
#pragma unroll
    for (int o = 16; o > 0; o >>= 1) v += __shfl_xor_sync(0xffffffffu, v, o);
    if ((threadIdx.x & 31) == 0) ws[threadIdx.x >> 5] = v;
    __syncthreads();
    if (threadIdx.x < 8) {
        int x = ws[threadIdx.x];
#pragma unroll
        for (int o = 4; o > 0; o >>= 1) x += __shfl_xor_sync(0xffu, x, o);
        if (threadIdx.x == 0) g_bsum[hop][blockIdx.x] = x;
    }
}
__global__ void bscan3()   // grid 3: exclusive scan per hop
{
    __shared__ int sh[256];
    int hop = blockIdx.x;
    int t = threadIdx.x;
    int orig = (t < NB) ? g_bsum[hop][t] : 0;
    sh[t] = orig;
    __syncthreads();
#pragma unroll
    for (int o = 1; o < 256; o <<= 1) {
        int v = (t >= o) ? sh[t - o] : 0;
        __syncthreads();
        sh[t] += v;
        __syncthreads();
    }
    if (t < NB) g_bsum[hop][t] = sh[t] - orig;
}
__global__ void rowptr3()
{
    __shared__ int sh[256];
    int hop = blockIdx.y;
    int t = threadIdx.x;
    int i = blockIdx.x * 256 + t;
    int d = (i < Nn) ? g_deg[hop][i] : 0;
    sh[t] = d;
    __syncthreads();
#pragma unroll
    for (int o = 1; o < 256; o <<= 1) {
        int v = (t >= o) ? sh[t - o] : 0;
        __syncthreads();
        sh[t] += v;
        __syncthreads();
    }
    if (i < Nn) {
        int rp = g_bsum[hop][blockIdx.x] + sh[t] - d;
        g_rp[hop][i] = rp;
        g_cur[hop][i] = rp;
    }
}
__global__ void fill3(const int* __restrict__ edges)
{
    int hop = blockIdx.y;
    int e = blockIdx.x * blockDim.x + threadIdx.x;
    if (e >= Ee) return;
    const int* src = edges + (size_t)hop * 2 * Ee;
    const int* dst = src + Ee;
    int pos = atomicAdd(&g_cur[hop][dst[e]], 1);
    g_csrc[hop][pos] = src[e];
}

// ---------------- GEMM (multi-hop via blockIdx.y; B double-buffered) ----------
// grid (NRB, 2*nhop): hop = blockIdx.y>>1, colBase = (blockIdx.y&1)*128
// mode bit0: leaky(0.01); bit2: emit alphas; bit3: write h split;
// bit4: per-hop bbias (bbias += hop*256); A slot per hop when aHop!=0
#define SM_AH 0
#define SM_AL 16384
#define SM_B0 32768
#define SM_B1 65536
#define SM_TOTAL 98304

__global__ void __launch_bounds__(256, 2) gemm_mma(
    const __nv_bfloat16* __restrict__ Ah, const __nv_bfloat16* __restrict__ Al,
    int aHop, int gidxBase, const float* __restrict__ bbias,
    const float* __restrict__ attS, const float* __restrict__ attD,
    float* __restrict__ C, int M, int mode, float scale)
{
    extern __shared__ char smem[];
    const uint32_t sb = smem_to_u32(smem);
    const int tid = threadIdx.x, wid = tid >> 5, lane = tid & 31;
    const int hop = blockIdx.y >> 1;
    const int rowBase = blockIdx.x * 128;
    const int colBase = (blockIdx.y & 1) * 128;
    const int warpM = (wid & 1) * 64;
    const int warpN = (wid >> 1) * 32;

    const char* bh = (const char*)g_bh + (size_t)(gidxBase + hop) * 131072u + (size_t)colBase * 128u;
    const char* bl = (const char*)g_bl + (size_t)(gidxBase + hop) * 131072u + (size_t)colBase * 128u;
    const size_t aoff = (size_t)blockIdx.x * 65536u + (aHop ? (size_t)hop * (SLOT * 2) : 0);
    const char* ah = (const char*)Ah + aoff;
    const char* al = (const char*)Al + aoff;
    C += (size_t)hop * Nn * 256;
    if (mode & 16) bbias += hop * 256;

    float acc[4][4][4];
#pragma unroll
    for (int i = 0; i < 4; i++)
#pragma unroll
        for (int j = 0; j < 4; j++)
#pragma unroll
            for (int c = 0; c < 4; c++) acc[i][j][c] = 0.f;

    const uint32_t xorA = (uint32_t)((lane & 7) << 4);
    const uint32_t aRow = (uint32_t)(warpM + (lane & 15));
    const uint32_t aSel = (uint32_t)((lane >> 4) << 4);
    // B via ldsm4: lanes 0-7 -> (j, k-lo), 8-15 -> (j, k-hi), 16-23 -> (j+1, k-lo), 24-31 -> (j+1, k-hi)
    const uint32_t bRow4 = (uint32_t)(warpN + (lane & 7) + ((lane >> 4) << 3));
    const uint32_t bSel4 = (uint32_t)(((lane >> 3) & 1) << 4);

    // ---- copy helpers ----
    auto cpA = [&](int kc) {
        const char* sah = ah + (size_t)kc * 16384;
        const char* sal = al + (size_t)kc * 16384;
#pragma unroll
        for (int it = 0; it < 4; it++) {
            uint32_t j = (uint32_t)(tid + it * 256) * 16u;
            CP_ASYNC16(sb + SM_AH + j, sah + j);
            CP_ASYNC16(sb + SM_AL + j, sal + j);
        }
    };
    auto cpB = [&](int kc, uint32_t bbase) {
        const char* sbh = bh + (size_t)kc * 32768;
        const char* sbl = bl + (size_t)kc * 32768;
#pragma unroll
        for (int it = 0; it < 4; it++) {     // 16KB BH + 16KB BL per buffer
            uint32_t j = (uint32_t)(tid + it * 256) * 16u;
            CP_ASYNC16(sb + bbase + j, sbh + j);
            CP_ASYNC16(sb + bbase + 16384 + j, sbl + j);
        }
    };

    // ---- prologue: A(0) + B(0) ----
    cpA(0);
    cpB(0, SM_B0);
    CP_COMMIT();
    CP_WAIT0();
    __syncthreads();

    for (int kc = 0; kc < 4; kc++) {
        const uint32_t bbase = (kc & 1) ? SM_B1 : SM_B0;
        if (kc < 3) {
            cpB(kc + 1, bbase ^ (SM_B0 ^ SM_B1));
            CP_COMMIT();
        }
#pragma unroll
        for (int ks = 0; ks < 4; ks++) {
            uint32_t ahf[4][4], alf[4][4], bhf[4][2], blf[4][2];
            const uint32_t kOffA = (uint32_t)(ks * 32) + aSel;
            const uint32_t kOffB = (uint32_t)(ks * 32) + bSel4;
#pragma unroll
            for (int i = 0; i < 4; i++) {
                uint32_t off = (((aRow + i * 16) * 128u + kOffA) ^ xorA);
                ldsm4(ahf[i], sb + SM_AH + off);
                ldsm4(alf[i], sb + SM_AL + off);
            }
#pragma unroll
            for (int jp = 0; jp < 2; jp++) {   // j-pairs {0,1}, {2,3}
                uint32_t off = (((bRow4 + jp * 16) * 128u + kOffB) ^ xorA);
                uint32_t rh[4], rl[4];
                ldsm4(rh, sb + bbase + off);
                ldsm4(rl, sb + bbase + 16384 + off);
                bhf[jp * 2][0] = rh[0];     bhf[jp * 2][1] = rh[1];
                bhf[jp * 2 + 1][0] = rh[2]; bhf[jp * 2 + 1][1] = rh[3];
                blf[jp * 2][0] = rl[0];     blf[jp * 2][1] = rl[1];
                blf[jp * 2 + 1][0] = rl[2]; blf[jp * 2 + 1][1] = rl[3];
            }
#pragma unroll
            for (int i = 0; i < 4; i++)
#pragma unroll
                for (int j = 0; j < 4; j++) mma16816(acc[i][j], ahf[i], bhf[j]);
#pragma unroll
            for (int i = 0; i < 4; i++)
#pragma unroll
                for (int j = 0; j < 4; j++) mma16816(acc[i][j], ahf[i], blf[j]);
#pragma unroll
            for (int i = 0; i < 4; i++)
#pragma unroll
                for (int j = 0; j < 4; j++) mma16816(acc[i][j], alf[i], bhf[j]);
        }
        if (kc < 3) {
            __syncthreads();       // all MMA(kc) reads of A buffer done
            cpA(kc + 1);
            CP_COMMIT();
            CP_WAIT0();
            __syncthreads();
        }
    }

    // ---- epilogue ----
    const int tg = lane >> 2;
    const int tc = (lane & 3) * 2;
    const int head = (blockIdx.y & 1) * 4 + (wid >> 1);
#pragma unroll
    for (int i = 0; i < 4; i++) {
        int rloc = warpM + i * 16 + tg;
        int r0 = rowBase + rloc;
        float as0 = 0.f, ad0 = 0.f, as1 = 0.f, ad1 = 0.f;
#pragma unroll
        for (int j = 0; j < 4; j++) {
            int col = colBase + warpN + j * 8 + tc;
            float b0 = bbias ? bbias[col] : 0.f;
            float b1 = bbias ? bbias[col + 1] : 0.f;
            float v0 = acc[i][j][0] + b0, v1 = acc[i][j][1] + b1;
            float v2 = acc[i][j][2] + b0, v3 = acc[i][j][3] + b1;
            if (mode & 1) {
                v0 = (v0 > 0.f) ? v0 : 0.01f * v0;
                v1 = (v1 > 0.f) ? v1 : 0.01f * v1;
                v2 = (v2 > 0.f) ? v2 : 0.01f * v2;
                v3 = (v3 > 0.f) ? v3 : 0.01f * v3;
            }
            v0 *= scale; v1 *= scale; v2 *= scale; v3 *= scale;
            if (r0 < M)
                *(float2*)(C + (size_t)r0 * 256 + col) = make_float2(v0, v1);
            if (r0 + 8 < M)
                *(float2*)(C + (size_t)(r0 + 8) * 256 + col) = make_float2(v2, v3);
            if (mode & 8) {
                int kcq = col >> 6, kk = col & 63;
                size_t tb = ((size_t)blockIdx.x * 4 + kcq) * 16384;
                if (r0 < M) {
                    uint32_t so = SMEM_SWZ((uint32_t)(rloc * 128 + kk * 2));
                    __nv_bfloat162 hp, lp;
                    hp.x = __float2bfloat16(v0); hp.y = __float2bfloat16(v1);
                    lp.x = __float2bfloat16(v0 - __bfloat162float(hp.x));
                    lp.y = __float2bfloat16(v1 - __bfloat162float(hp.y));
                    *(uint32_t*)((char*)g_hh + tb + so) = *(uint32_t*)&hp;
                    *(uint32_t*)((char*)g_hl + tb + so) = *(uint32_t*)&lp;
                }
                if (r0 + 8 < M) {
                    uint32_t so = SMEM_SWZ((uint32_t)((rloc + 8) * 128 + kk * 2));
                    __nv_bfloat162 hp, lp;
                    hp.x = __float2bfloat16(v2); hp.y = __float2bfloat16(v3);
                    lp.x = __float2bfloat16(v2 - __bfloat162float(hp.x));
                    lp.y = __float2bfloat16(v3 - __bfloat162float(hp.y));
                    *(uint32_t*)((char*)g_hh + tb + so) = *(uint32_t*)&hp;
                    *(uint32_t*)((char*)g_hl + tb + so) = *(uint32_t*)&lp;
                }
            }
            if (mode & 4) {
                float s0 = attS[hop * 256 + col], s1 = attS[hop * 256 + col + 1];
                float d0 = attD[hop * 256 + col], d1 = attD[hop * 256 + col + 1];
                as0 += v0 * s0 + v1 * s1;  ad0 += v0 * d0 + v1 * d1;
                as1 += v2 * s0 + v3 * s1;  ad1 += v2 * d0 + v3 * d1;
            }
        }
        if (mode & 4) {
#pragma unroll
            for (int o = 1; o <= 2; o <<= 1) {
                as0 += __shfl_xor_sync(0xffffffffu, as0, o);
                ad0 += __shfl_xor_sync(0xffffffffu, ad0, o);
                as1 += __shfl_xor_sync(0xffffffffu, as1, o);
                ad1 += __shfl_xor_sync(0xffffffffu, ad1, o);
            }
            if ((lane & 3) == 0) {
                size_t ab = (size_t)hop * Nn * 8;
                if (r0 < M)     { g_as[ab + (size_t)r0 * 8 + head] = as0;       g_ad[ab + (size_t)r0 * 8 + head] = ad0; }
                if (r0 + 8 < M) { g_as[ab + (size_t)(r0 + 8) * 8 + head] = as1; g_ad[ab + (size_t)(r0 + 8) * 8 + head] = ad1; }
            }
        }
    }
}

// ---------------- attention softmax (3 hops batched) ----------------
__global__ void attn_csr3()
{
    int t = blockIdx.x * blockDim.x + threadIdx.x;
    if (t >= Nn * 8) return;
    int hop = blockIdx.y;
    int d = t >> 3, h = t & 7;
    int start = g_rp[hop][d];
    int end = start + g_deg[hop][d];
    const float* as = g_as + (size_t)hop * Nn * 8;
    float* ge = g_e + (size_t)hop * Ee * 8;
    float adv = g_ad[(size_t)hop * Nn * 8 + (size_t)d * 8 + h];
    float m = -3.4e38f;
    for (int j = start; j < end; j++) {
        int s = g_csrc[hop][j];
        float lg = as[(size_t)s * 8 + h] + adv;
        lg = (lg > 0.f) ? lg : 0.2f * lg;
        ge[(size_t)j * 8 + h] = lg;
        m = fmaxf(m, lg);
    }
    float sum = 0.f;
    for (int j = start; j < end; j++) {
        float v = __expf(ge[(size_t)j * 8 + h] - m);
        ge[(size_t)j * 8 + h] = v;
        sum += v;
    }
    g_s[(size_t)hop * Nn * 8 + (size_t)d * 8 + h] = sum;
}

// ---------------- aggregate (3 hops batched); writes agg bf16 split -------------
__global__ void edge3_csr3()
{
    int gt = blockIdx.x * blockDim.x + threadIdx.x;
    int d = gt >> 5, lane = gt & 31;
    if (d >= Nn) return;
    int hop = blockIdx.y;
    int start = g_rp[hop][d];
    int end = start + g_deg[hop][d];
    const float* ge = g_e + (size_t)hop * Ee * 8;
    const float* h1 = g_h1 + (size_t)hop * Nn * 256;
    int h0 = lane >> 3, h1i = 4 + (lane >> 3);
    float i0 = 1.f / (g_s[(size_t)hop * Nn * 8 + (size_t)d * 8 + h0] + 1e-16f);
    float i1 = 1.f / (g_s[(size_t)hop * Nn * 8 + (size_t)d * 8 + h1i] + 1e-16f);
    float4 a0 = make_float4(0.f, 0.f, 0.f, 0.f);
    float4 a1 = a0;
    for (int j = start; j < end; j++) {
        int s = g_csrc[hop][j];
        float al0 = ge[(size_t)j * 8 + h0] * i0;
        float al1 = ge[(size_t)j * 8 + h1i] * i1;
        const float* hs = h1 + (size_t)s * 256;
        float4 v0 = *(const float4*)(hs + lane * 4);
        float4 v1 = *(const float4*)(hs + 128 + lane * 4);
        a0.x += al0 * v0.x; a0.y += al0 * v0.y; a0.z += al0 * v0.z; a0.w += al0 * v0.w;
        a1.x += al1 * v1.x; a1.y += al1 * v1.y; a1.z += al1 * v1.z; a1.w += al1 * v1.w;
    }
    int rb = d >> 7, rloc = d & 127;
    int c0 = lane * 4;
    int kc0 = c0 >> 6, kk0 = c0 & 63;
    uint2 hi0, lo0, hi1, lo1;
    split4(a0, hi0, lo0);
    split4(a1, hi1, lo1);
    size_t sbase = (size_t)hop * SLOT * 2;
    size_t b0 = sbase + ((size_t)rb * 4 + kc0) * 16384 + SMEM_SWZ((uint32_t)(rloc * 128 + kk0 * 2));
    size_t b1 = sbase + ((size_t)rb * 4 + kc0 + 2) * 16384 + SMEM_SWZ((uint32_t)(rloc * 128 + kk0 * 2));
    *(uint2*)((char*)g_gh + b0) = hi0;  *(uint2*)((char*)g_gl + b0) = lo0;
    *(uint2*)((char*)g_gh + b1) = hi1;  *(uint2*)((char*)g_gl + b1) = lo1;
}

// ---------------- layernorm of decay-weighted hop sum + residual ----------------
__global__ void ln_kernel(const float* __restrict__ acc3,
                          const float* __restrict__ scale,
                          const float* __restrict__ bias,
                          const float* __restrict__ res,
                          float* __restrict__ out, int writeSplit)
{
    int gt = blockIdx.x * blockDim.x + threadIdx.x;
    int n = gt >> 5;
    int lane = gt & 31;
    if (n >= Nn) return;
    const float d1 = 0.60653065971263342f, d2 = 0.36787944117144233f;
    const float* a0p = acc3 + (size_t)n * 256;
    const float* a1p = a0p + (size_t)Nn * 256;
    const float* a2p = a1p + (size_t)Nn * 256;
    float4 v0, v1;
    {
        float4 x0 = *(const float4*)(a0p + lane * 4);
        float4 y0 = *(const float4*)(a1p + lane * 4);
        float4 z0 = *(const float4*)(a2p + lane * 4);
        v0.x = x0.x + d1 * y0.x + d2 * z0.x;
        v0.y = x0.y + d1 * y0.y + d2 * z0.y;
        v0.z = x0.z + d1 * y0.z + d2 * z0.z;
        v0.w = x0.w + d1 * y0.w + d2 * z0.w;
        float4 x1 = *(const float4*)(a0p + 128 + lane * 4);
        float4 y1 = *(const float4*)(a1p + 128 + lane * 4);
        float4 z1 = *(const float4*)(a2p + 128 + lane * 4);
        v1.x = x1.x + d1 * y1.x + d2 * z1.x;
        v1.y = x1.y + d1 * y1.y + d2 * z1.y;
        v1.z = x1.z + d1 * y1.z + d2 * z1.z;
        v1.w = x1.w + d1 * y1.w + d2 * z1.w;
    }
    float sm = v0.x + v0.y + v0.z + v0.w + v1.x + v1.y + v1.z + v1.w;
    float sq = v0.x * v0.x + v0.y * v0.y + v0.z * v0.z + v0.w * v0.w
             + v1.x * v1.x + v1.y * v1.y + v1.z * v1.z + v1.w * v1.w;
#pragma unroll
    for (int o = 16; o > 0; o >>= 1) {
        sm += __shfl_xor_sync(0xffffffffu, sm, o);
        sq += __shfl_xor_sync(0xffffffffu, sq, o);
    }
    float mu = sm * (1.f / 256.f);
    float var = sq * (1.f / 256.f) - mu * mu;
    float rstd = rsqrtf(var + 1e-5f);

    const float* rp = res + (size_t)n * 256;
    float4 r0 = *(const float4*)(rp + lane * 4);
    float4 r1 = *(const float4*)(rp + 128 + lane * 4);
    float4 sc0 = *(const float4*)(scale + lane * 4);
    float4 sc1 = *(const float4*)(scale + 128 + lane * 4);
    float4 b0 = *(const float4*)(bias + lane * 4);
    float4 b1 = *(const float4*)(bias + 128 + lane * 4);

    float4 o0, o1;
    o0.x = (v0.x - mu) * rstd * sc0.x + b0.x + r0.x;
    o0.y = (v0.y - mu) * rstd * sc0.y + b0.y + r0.y;
    o0.z = (v0.z - mu) * rstd * sc0.z + b0.z + r0.z;
    o0.w = (v0.w - mu) * rstd * sc0.w + b0.w + r0.w;
    o1.x = (v1.x - mu) * rstd * sc1.x + b1.x + r1.x;
    o1.y = (v1.y - mu) * rstd * sc1.y + b1.y + r1.y;
    o1.z = (v1.z - mu) * rstd * sc1.z + b1.z + r1.z;
    o1.w = (v1.w - mu) * rstd * sc1.w + b1.w + r1.w;

    float* op = out + (size_t)n * 256;
    *(float4*)(op + lane * 4) = o0;
    *(float4*)(op + 128 + lane * 4) = o1;

    if (writeSplit) {
        int rb = n >> 7, rloc = n & 127;
        int c0 = lane * 4;
        int kc0 = c0 >> 6, kk0 = c0 & 63;
        uint2 hi0, lo0, hi1, lo1;
        split4(o0, hi0, lo0);
        split4(o1, hi1, lo1);
        size_t q0 = ((size_t)rb * 4 + kc0) * 16384 + SMEM_SWZ((uint32_t)(rloc * 128 + kk0 * 2));
        size_t q1 = ((size_t)rb * 4 + kc0 + 2) * 16384 + SMEM_SWZ((uint32_t)(rloc * 128 + kk0 * 2));
        *(uint2*)((char*)g_hh + q0) = hi0;  *(uint2*)((char*)g_hl + q0) = lo0;
        *(uint2*)((char*)g_hh + q1) = hi1;  *(uint2*)((char*)g_hl + q1) = lo1;
    }
}

// ---------------- host driver ----------------
extern "C" void kernel_launch(void* const* d_in, const int* in_sizes, int n_in,
                              void* d_out, int out_size)
{
    const float* x        = (const float*)d_in[0];
    const int*   edges    = (const int*)  d_in[1];
    const float* lin1_w   = (const float*)d_in[2];
    const float* lin1_b   = (const float*)d_in[3];
    const float* gat_w    = (const float*)d_in[4];
    const float* att_src  = (const float*)d_in[5];
    const float* att_dst  = (const float*)d_in[6];
    const float* gat_bias = (const float*)d_in[7];
    const float* dec_w    = (const float*)d_in[8];
    const float* dec_b    = (const float*)d_in[9];
    const float* ln_scale = (const float*)d_in[10];
    const float* ln_bias  = (const float*)d_in[11];
    float* out = (float*)d_out;

    cudaFuncSetAttribute(gemm_mma, cudaFuncAttributeMaxDynamicSharedMemorySize, SM_TOTAL);

    float *p_h, *p_h1, *p_acc3, *p_bw;
    __nv_bfloat16 *p_hh, *p_hl, *p_gh, *p_gl;
    int *p_deg;
    cudaGetSymbolAddress((void**)&p_h,    g_h);
    cudaGetSymbolAddress((void**)&p_h1,   g_h1);
    cudaGetSymbolAddress((void**)&p_acc3, g_acc3);
    cudaGetSymbolAddress((void**)&p_bw,   g_bw);
    cudaGetSymbolAddress((void**)&p_hh,   g_hh);
    cudaGetSymbolAddress((void**)&p_hl,   g_hl);
    cudaGetSymbolAddress((void**)&p_gh,   g_gh);
    cudaGetSymbolAddress((void**)&p_gl,   g_gl);
    cudaGetSymbolAddress((void**)&p_deg,  g_deg);

    // preamble: zero deg, init bw, then one mega prep launch
    cudaMemsetAsync(p_deg, 0, 3 * (size_t)Nn * sizeof(int));
    cudaMemcpyAsync(p_bw, dec_b, 6 * 256 * sizeof(float), cudaMemcpyDeviceToDevice);
    prep_kernel<<<B_PREP, 256>>>(lin1_w, gat_w, dec_w, x, gat_bias, edges);

    bsum3<<<dim3(NB, 3), 256>>>();
    bscan3<<<3, 256>>>();
    rowptr3<<<dim3(NB, 3), 256>>>();
    fill3<<<dim3((Ee + 255) / 256, 3), 256>>>(edges);

    // h = leaky(x @ lin1_w + lin1_b); writes fp32 h + h split
    gemm_mma<<<dim3(NRB, 2), 256, SM_TOTAL>>>(p_gh, p_gl, 0, 0, lin1_b,
                                              nullptr, nullptr, p_h, Nn, 1 | 8, 1.f);

    for (int l = 0; l < 2; l++) {
        // all 3 hop GEMMs: h1[hop] = h @ W[l,hop], fused alphas
        gemm_mma<<<dim3(NRB, 6), 256, SM_TOTAL>>>(p_hh, p_hl, 0, 1 + l * 3, nullptr,
                                                  att_src + (size_t)l * 3 * 256,
                                                  att_dst + (size_t)l * 3 * 256,
                                                  p_h1, Nn, 4, 1.f);
        attn_csr3<<<dim3((Nn * 8 + 255) / 256, 3), 256>>>();
        edge3_csr3<<<dim3((Nn * 32 + 255) / 256, 3), 256>>>();

        // all 3 dec GEMMs: acc3[hop] = leaky(agg[hop] @ dec_w + bw), decay in LN
        gemm_mma<<<dim3(NRB, 6), 256, SM_TOTAL>>>(p_gh, p_gl, 1, 7 + l * 3,
                                                  p_bw + l * 3 * 256,
                                                  nullptr, nullptr,
                                                  p_acc3, Nn, 1 | 16, 1.f);

        ln_kernel<<<(Nn * 32 + 255) / 256, 256>>>(
            p_acc3, ln_scale + (size_t)l * 256, ln_bias + (size_t)l * 256,
            p_h, (l == 0) ? p_h : out, (l == 0) ? 1 : 0);
    }
}

// round 15
// speedup vs baseline: 1.1909x; 1.1577x over previous
#include <cuda_runtime.h>
#include <cuda_fp16.h>
#include <cstdint>
#include <cstddef>

#define Nn 50000
#define Ee 300000
#define DH 256
#define NB 196          // ceil(Nn/256)
#define NRB 391         // ceil(Nn/128) row blocks
#define SLOT ((size_t)NRB * 32768)   // fp16 elements per A-split slot

// prep_kernel block ranges
#define B_CONVW 3328    // 13*65536/256
#define B_CONVA 12500   // Nn*64/256
#define B_HISTH 1172    // ceil(Ee/256)
#define B_HIST  (3 * B_HISTH)
#define B_BIASW 48      // 6 lk * 8 kslices
#define B_PREP  (B_CONVW + B_CONVA + B_HIST + B_BIASW)

// ================= helpers =================
__device__ __forceinline__ uint32_t smem_to_u32(const void* p) {
    uint32_t a;
    asm("{ .reg .u64 t; cvta.to.shared.u64 t, %1; cvt.u32.u64 %0, t; }" : "=r"(a) : "l"(p));
    return a;
}
__device__ __forceinline__ void ldsm4(uint32_t* r, uint32_t addr) {
    asm volatile("ldmatrix.sync.aligned.m8n8.x4.shared.b16 {%0,%1,%2,%3}, [%4];"
        : "=r"(r[0]), "=r"(r[1]), "=r"(r[2]), "=r"(r[3]) : "r"(addr));
}
__device__ __forceinline__ void mma16816h(float* c, const uint32_t* a, const uint32_t* b) {
    asm volatile("mma.sync.aligned.m16n8k16.row.col.f32.f16.f16.f32 "
        "{%0,%1,%2,%3}, {%4,%5,%6,%7}, {%8,%9}, {%0,%1,%2,%3};"
        : "+f"(c[0]), "+f"(c[1]), "+f"(c[2]), "+f"(c[3])
        : "r"(a[0]), "r"(a[1]), "r"(a[2]), "r"(a[3]), "r"(b[0]), "r"(b[1]));
}
#define CP_ASYNC16(sa, gp) \
    asm volatile("cp.async.cg.shared.global [%0], [%1], 16;" :: "r"(sa), "l"(gp))
#define CP_COMMIT() asm volatile("cp.async.commit_group;")
#define CP_WAIT0()  asm volatile("cp.async.wait_group 0;")
#define SMEM_SWZ(o) ((o) ^ ((((uint32_t)(o)) >> 3) & 0x70u))

// fp32x4 -> fp16 hi/lo pairs (hi = RN(v), lo = RN(v - hi))
__device__ __forceinline__ void split4h(float4 v, uint2& hi, uint2& lo) {
    __half2 h0 = __floats2half2_rn(v.x, v.y);
    __half2 h1 = __floats2half2_rn(v.z, v.w);
    __half2 l0 = __floats2half2_rn(v.x - __low2float(h0), v.y - __high2float(h0));
    __half2 l1 = __floats2half2_rn(v.z - __low2float(h1), v.w - __high2float(h1));
    hi.x = *(uint32_t*)&h0;  hi.y = *(uint32_t*)&h1;
    lo.x = *(uint32_t*)&l0;  lo.y = *(uint32_t*)&l1;
}

// ================= scratch (static device globals) =================
__device__ float g_h   [(size_t)Nn * DH];        // fp32 h (residual path)
__device__ float g_h1  [3 * (size_t)Nn * DH];    // per-hop GEMM output
__device__ float g_acc3[3 * (size_t)Nn * DH];    // per-hop dec output
__device__ float g_as [3 * (size_t)Nn * 8];
__device__ float g_ad [3 * (size_t)Nn * 8];
__device__ float g_s  [3 * (size_t)Nn * 8];
__device__ float g_e  [3 * (size_t)Ee * 8];
__device__ float g_bw [6 * 256];                 // folded dec column bias
// weights: 13 matrices, [4 kc][256 n][64 k] fp16 swizzled (single plane)
__device__ __half g_bh[13 * 65536];
// A splits (fp16 hi/lo): h (1 slot) + x/agg (3 slots, per hop)
__device__ __half g_hh[SLOT];
__device__ __half g_hl[SLOT];
__device__ __half g_gh[3 * SLOT];
__device__ __half g_gl[3 * SLOT];
// CSR (by dst)
__device__ int g_deg [3][Nn];
__device__ int g_rp  [3][Nn];
__device__ int g_csrc[3][Ee];
__device__ int g_cur [3][Nn];
__device__ int g_bsum[3][256];

// ---------------- prep: convw(13) + conva + hist3 + biasw, one launch ----------
__global__ void prep_kernel(const float* __restrict__ lin1_w,
                            const float* __restrict__ gat_w,
                            const float* __restrict__ dec_w,
                            const float* __restrict__ x,
                            const float* __restrict__ gat_bias,
                            const int* __restrict__ edges)
{
    int b = blockIdx.x;
    int tid = threadIdx.x;
    if (b < B_CONVW) {
        // weight convert: W[k][n] -> swizzled fp16
        int id = b * 256 + tid;
        int g = id >> 16;
        int r = id & 65535;
        int n = r & 255;
        int kf = r >> 8;
        const float* W = (g == 0) ? (lin1_w + r)
                       : (g < 7)  ? (gat_w + (size_t)(g - 1) * 65536 + r)
                                  : (dec_w + (size_t)(g - 7) * 65536 + r);
        float v = *W;
        int kc = kf >> 6, kk = kf & 63;
        uint32_t off = (uint32_t)kc * 32768u + SMEM_SWZ((uint32_t)(n * 128 + kk * 2));
        size_t base = (size_t)g * 131072u;
        *(__half*)((char*)g_bh + base + off) = __float2half(v);
        return;
    }
    b -= B_CONVW;
    if (b < B_CONVA) {
        // x split into slot 0 of g_gh/g_gl
        int id = b * 256 + tid;
        int r = id >> 6, q = id & 63;
        float4 v = *(const float4*)(x + (size_t)r * 256 + q * 4);
        uint2 hi, lo;
        split4h(v, hi, lo);
        int rb = r >> 7, rloc = r & 127;
        int kc = q >> 4, kk = (q & 15) * 4;
        size_t off = ((size_t)rb * 4 + kc) * 16384 + SMEM_SWZ((uint32_t)(rloc * 128 + kk * 2));
        *(uint2*)((char*)g_gh + off) = hi;
        *(uint2*)((char*)g_gl + off) = lo;
        return;
    }
    b -= B_CONVA;
    if (b < B_HIST) {
        int hop = b / B_HISTH;
        int e = (b - hop * B_HISTH) * 256 + tid;
        if (e < Ee) atomicAdd(&g_deg[hop][edges[(size_t)hop * 2 * Ee + Ee + e]], 1);
        return;
    }
    b -= B_HIST;
    {
        // biasw: g_bw += gat_bias @ dec_w  (g_bw pre-initialized with dec_b)
        int lk = b >> 3;
        int k0 = (b & 7) * 32;
        const float* W = dec_w + (size_t)lk * 65536;
        const float* gb = gat_bias + lk * 256;
        float acc = 0.f;
#pragma unroll
        for (int k = 0; k < 32; k++) acc += gb[k0 + k] * W[(k0 + k) * 256 + tid];
        atomicAdd(&g_bw[lk * 256 + tid], acc);
    }
}

// ---------------- CSR scan chain ----------------
__global__ void bsum3()
{
    __shared__ int ws[8];
    int hop = blockIdx.y;
    int i = blockIdx.x * 256 + threadIdx.x;
    int v = (i < Nn) ? g_deg[hop][i] : 0;
#pragma unroll
    for (int o = 16; o > 0; o >>= 1) v += __shfl_xor_sync(0xffffffffu, v, o);
    if ((threadIdx.x & 31) == 0) ws[threadIdx.x >> 5] = v;
    __syncthreads();
    if (threadIdx.x < 8) {
        int x = ws[threadIdx.x];
#pragma unroll
        for (int o = 4; o > 0; o >>= 1) x += __shfl_xor_sync(0xffu, x, o);
        if (threadIdx.x == 0) g_bsum[hop][blockIdx.x] = x;
    }
}
__global__ void bscan3()   // grid 3: exclusive scan per hop
{
    __shared__ int sh[256];
    int hop = blockIdx.x;
    int t = threadIdx.x;
    int orig = (t < NB) ? g_bsum[hop][t] : 0;
    sh[t] = orig;
    __syncthreads();
#pragma unroll
    for (int o = 1; o < 256; o <<= 1) {
        int v = (t >= o) ? sh[t - o] : 0;
        __syncthreads();
        sh[t] += v;
        __syncthreads();
    }
    if (t < NB) g_bsum[hop][t] = sh[t] - orig;
}
__global__ void rowptr3()
{
    __shared__ int sh[256];
    int hop = blockIdx.y;
    int t = threadIdx.x;
    int i = blockIdx.x * 256 + t;
    int d = (i < Nn) ? g_deg[hop][i] : 0;
    sh[t] = d;
    __syncthreads();
#pragma unroll
    for (int o = 1; o < 256; o <<= 1) {
        int v = (t >= o) ? sh[t - o] : 0;
        __syncthreads();
        sh[t] += v;
        __syncthreads();
    }
    if (i < Nn) {
        int rp = g_bsum[hop][blockIdx.x] + sh[t] - d;
        g_rp[hop][i] = rp;
        g_cur[hop][i] = rp;
    }
}
__global__ void fill3(const int* __restrict__ edges)
{
    int hop = blockIdx.y;
    int e = blockIdx.x * blockDim.x + threadIdx.x;
    if (e >= Ee) return;
    const int* src = edges + (size_t)hop * 2 * Ee;
    const int* dst = src + Ee;
    int pos = atomicAdd(&g_cur[hop][dst[e]], 1);
    g_csrc[hop][pos] = src[e];
}

// ---------------- GEMM: fp16 2-pass (Ah+Al)·Bh; B double-buffered ----------
// grid (NRB, 2*nhop): hop = blockIdx.y>>1, colBase = (blockIdx.y&1)*128
// mode bit0: leaky(0.01); bit2: emit alphas; bit3: write h split;
// bit4: per-hop bbias (bbias += hop*256); A slot per hop when aHop!=0
#define SM_AH 0
#define SM_AL 16384
#define SM_B0 32768
#define SM_B1 49152
#define SM_TOTAL 65536

__global__ void __launch_bounds__(256, 2) gemm_mma(
    const __half* __restrict__ Ah, const __half* __restrict__ Al,
    int aHop, int gidxBase, const float* __restrict__ bbias,
    const float* __restrict__ attS, const float* __restrict__ attD,
    float* __restrict__ C, int M, int mode, float scale)
{
    extern __shared__ char smem[];
    const uint32_t sb = smem_to_u32(smem);
    const int tid = threadIdx.x, wid = tid >> 5, lane = tid & 31;
    const int hop = blockIdx.y >> 1;
    const int rowBase = blockIdx.x * 128;
    const int colBase = (blockIdx.y & 1) * 128;
    const int warpM = (wid & 1) * 64;
    const int warpN = (wid >> 1) * 32;

    const char* bh = (const char*)g_bh + (size_t)(gidxBase + hop) * 131072u + (size_t)colBase * 128u;
    const size_t aoff = (size_t)blockIdx.x * 65536u + (aHop ? (size_t)hop * (SLOT * 2) : 0);
    const char* ah = (const char*)Ah + aoff;
    const char* al = (const char*)Al + aoff;
    C += (size_t)hop * Nn * 256;
    if (mode & 16) bbias += hop * 256;

    float acc[4][4][4];
#pragma unroll
    for (int i = 0; i < 4; i++)
#pragma unroll
        for (int j = 0; j < 4; j++)
#pragma unroll
            for (int c = 0; c < 4; c++) acc[i][j][c] = 0.f;

    const uint32_t xorA = (uint32_t)((lane & 7) << 4);
    const uint32_t aRow = (uint32_t)(warpM + (lane & 15));
    const uint32_t aSel = (uint32_t)((lane >> 4) << 4);
    // B via ldsm4 j-pairs
    const uint32_t bRow4 = (uint32_t)(warpN + (lane & 7) + ((lane >> 4) << 3));
    const uint32_t bSel4 = (uint32_t)(((lane >> 3) & 1) << 4);

    // ---- copy helpers ----
    auto cpA = [&](int kc) {
        const char* sah = ah + (size_t)kc * 16384;
        const char* sal = al + (size_t)kc * 16384;
#pragma unroll
        for (int it = 0; it < 4; it++) {
            uint32_t j = (uint32_t)(tid + it * 256) * 16u;
            CP_ASYNC16(sb + SM_AH + j, sah + j);
            CP_ASYNC16(sb + SM_AL + j, sal + j);
        }
    };
    auto cpB = [&](int kc, uint32_t bbase) {
        const char* sbh = bh + (size_t)kc * 32768;
#pragma unroll
        for (int it = 0; it < 4; it++) {     // 16KB per buffer
            uint32_t j = (uint32_t)(tid + it * 256) * 16u;
            CP_ASYNC16(sb + bbase + j, sbh + j);
        }
    };

    // ---- prologue: A(0) + B(0) ----
    cpA(0);
    cpB(0, SM_B0);
    CP_COMMIT();
    CP_WAIT0();
    __syncthreads();

    for (int kc = 0; kc < 4; kc++) {
        const uint32_t bbase = (kc & 1) ? SM_B1 : SM_B0;
        if (kc < 3) {
            cpB(kc + 1, bbase ^ (SM_B0 ^ SM_B1));
            CP_COMMIT();
        }
#pragma unroll
        for (int ks = 0; ks < 4; ks++) {
            uint32_t ahf[4][4], alf[4][4], bhf[4][2];
            const uint32_t kOffA = (uint32_t)(ks * 32) + aSel;
            const uint32_t kOffB = (uint32_t)(ks * 32) + bSel4;
#pragma unroll
            for (int i = 0; i < 4; i++) {
                uint32_t off = (((aRow + i * 16) * 128u + kOffA) ^ xorA);
                ldsm4(ahf[i], sb + SM_AH + off);
                ldsm4(alf[i], sb + SM_AL + off);
            }
#pragma unroll
            for (int jp = 0; jp < 2; jp++) {   // j-pairs {0,1}, {2,3}
                uint32_t off = (((bRow4 + jp * 16) * 128u + kOffB) ^ xorA);
                uint32_t rh[4];
                ldsm4(rh, sb + bbase + off);
                bhf[jp * 2][0] = rh[0];     bhf[jp * 2][1] = rh[1];
                bhf[jp * 2 + 1][0] = rh[2]; bhf[jp * 2 + 1][1] = rh[3];
            }
#pragma unroll
            for (int i = 0; i < 4; i++)
#pragma unroll
                for (int j = 0; j < 4; j++) mma16816h(acc[i][j], ahf[i], bhf[j]);
#pragma unroll
            for (int i = 0; i < 4; i++)
#pragma unroll
                for (int j = 0; j < 4; j++) mma16816h(acc[i][j], alf[i], bhf[j]);
        }
        if (kc < 3) {
            __syncthreads();       // all MMA(kc) reads of A buffer done
            cpA(kc + 1);
            CP_COMMIT();
            CP_WAIT0();
            __syncthreads();
        }
    }

    // ---- epilogue ----
    const int tg = lane >> 2;
    const int tc = (lane & 3) * 2;
    const int head = (blockIdx.y & 1) * 4 + (wid >> 1);
#pragma unroll
    for (int i = 0; i < 4; i++) {
        int rloc = warpM + i * 16 + tg;
        int r0 = rowBase + rloc;
        float as0 = 0.f, ad0 = 0.f, as1 = 0.f, ad1 = 0.f;
#pragma unroll
        for (int j = 0; j < 4; j++) {
            int col = colBase + warpN + j * 8 + tc;
            float b0 = bbias ? bbias[col] : 0.f;
            float b1 = bbias ? bbias[col + 1] : 0.f;
            float v0 = acc[i][j][0] + b0, v1 = acc[i][j][1] + b1;
            float v2 = acc[i][j][2] + b0, v3 = acc[i][j][3] + b1;
            if (mode & 1) {
                v0 = (v0 > 0.f) ? v0 : 0.01f * v0;
                v1 = (v1 > 0.f) ? v1 : 0.01f * v1;
                v2 = (v2 > 0.f) ? v2 : 0.01f * v2;
                v3 = (v3 > 0.f) ? v3 : 0.01f * v3;
            }
            v0 *= scale; v1 *= scale; v2 *= scale; v3 *= scale;
            if (r0 < M)
                *(float2*)(C + (size_t)r0 * 256 + col) = make_float2(v0, v1);
            if (r0 + 8 < M)
                *(float2*)(C + (size_t)(r0 + 8) * 256 + col) = make_float2(v2, v3);
            if (mode & 8) {
                int kcq = col >> 6, kk = col & 63;
                size_t tb = ((size_t)blockIdx.x * 4 + kcq) * 16384;
                if (r0 < M) {
                    uint32_t so = SMEM_SWZ((uint32_t)(rloc * 128 + kk * 2));
                    __half2 hp = __floats2half2_rn(v0, v1);
                    __half2 lp = __floats2half2_rn(v0 - __low2float(hp), v1 - __high2float(hp));
                    *(uint32_t*)((char*)g_hh + tb + so) = *(uint32_t*)&hp;
                    *(uint32_t*)((char*)g_hl + tb + so) = *(uint32_t*)&lp;
                }
                if (r0 + 8 < M) {
                    uint32_t so = SMEM_SWZ((uint32_t)((rloc + 8) * 128 + kk * 2));
                    __half2 hp = __floats2half2_rn(v2, v3);
                    __half2 lp = __floats2half2_rn(v2 - __low2float(hp), v3 - __high2float(hp));
                    *(uint32_t*)((char*)g_hh + tb + so) = *(uint32_t*)&hp;
                    *(uint32_t*)((char*)g_hl + tb + so) = *(uint32_t*)&lp;
                }
            }
            if (mode & 4) {
                float s0 = attS[hop * 256 + col], s1 = attS[hop * 256 + col + 1];
                float d0 = attD[hop * 256 + col], d1 = attD[hop * 256 + col + 1];
                as0 += v0 * s0 + v1 * s1;  ad0 += v0 * d0 + v1 * d1;
                as1 += v2 * s0 + v3 * s1;  ad1 += v2 * d0 + v3 * d1;
            }
        }
        if (mode & 4) {
#pragma unroll
            for (int o = 1; o <= 2; o <<= 1) {
                as0 += __shfl_xor_sync(0xffffffffu, as0, o);
                ad0 += __shfl_xor_sync(0xffffffffu, ad0, o);
                as1 += __shfl_xor_sync(0xffffffffu, as1, o);
                ad1 += __shfl_xor_sync(0xffffffffu, ad1, o);
            }
            if ((lane & 3) == 0) {
                size_t ab = (size_t)hop * Nn * 8;
                if (r0 < M)     { g_as[ab + (size_t)r0 * 8 + head] = as0;       g_ad[ab + (size_t)r0 * 8 + head] = ad0; }
                if (r0 + 8 < M) { g_as[ab + (size_t)(r0 + 8) * 8 + head] = as1; g_ad[ab + (size_t)(r0 + 8) * 8 + head] = ad1; }
            }
        }
    }
}

// ---------------- attention softmax (3 hops batched) ----------------
__global__ void attn_csr3()
{
    int t = blockIdx.x * blockDim.x + threadIdx.x;
    if (t >= Nn * 8) return;
    int hop = blockIdx.y;
    int d = t >> 3, h = t & 7;
    int start = g_rp[hop][d];
    int end = start + g_deg[hop][d];
    const float* as = g_as + (size_t)hop * Nn * 8;
    float* ge = g_e + (size_t)hop * Ee * 8;
    float adv = g_ad[(size_t)hop * Nn * 8 + (size_t)d * 8 + h];
    float m = -3.4e38f;
    for (int j = start; j < end; j++) {
        int s = g_csrc[hop][j];
        float lg = as[(size_t)s * 8 + h] + adv;
        lg = (lg > 0.f) ? lg : 0.2f * lg;
        ge[(size_t)j * 8 + h] = lg;
        m = fmaxf(m, lg);
    }
    float sum = 0.f;
    for (int j = start; j < end; j++) {
        float v = __expf(ge[(size_t)j * 8 + h] - m);
        ge[(size_t)j * 8 + h] = v;
        sum += v;
    }
    g_s[(size_t)hop * Nn * 8 + (size_t)d * 8 + h] = sum;
}

// ---------------- aggregate (3 hops batched); writes agg fp16 split -------------
__global__ void edge3_csr3()
{
    int gt = blockIdx.x * blockDim.x + threadIdx.x;
    int d = gt >> 5, lane = gt & 31;
    if (d >= Nn) return;
    int hop = blockIdx.y;
    int start = g_rp[hop][d];
    int end = start + g_deg[hop][d];
    const float* ge = g_e + (size_t)hop * Ee * 8;
    const float* h1 = g_h1 + (size_t)hop * Nn * 256;
    int h0 = lane >> 3, h1i = 4 + (lane >> 3);
    float i0 = 1.f / (g_s[(size_t)hop * Nn * 8 + (size_t)d * 8 + h0] + 1e-16f);
    float i1 = 1.f / (g_s[(size_t)hop * Nn * 8 + (size_t)d * 8 + h1i] + 1e-16f);
    float4 a0 = make_float4(0.f, 0.f, 0.f, 0.f);
    float4 a1 = a0;
    for (int j = start; j < end; j++) {
        int s = g_csrc[hop][j];
        float al0 = ge[(size_t)j * 8 + h0] * i0;
        float al1 = ge[(size_t)j * 8 + h1i] * i1;
        const float* hs = h1 + (size_t)s * 256;
        float4 v0 = *(const float4*)(hs + lane * 4);
        float4 v1 = *(const float4*)(hs + 128 + lane * 4);
        a0.x += al0 * v0.x; a0.y += al0 * v0.y; a0.z += al0 * v0.z; a0.w += al0 * v0.w;
        a1.x += al1 * v1.x; a1.y += al1 * v1.y; a1.z += al1 * v1.z; a1.w += al1 * v1.w;
    }
    int rb = d >> 7, rloc = d & 127;
    int c0 = lane * 4;
    int kc0 = c0 >> 6, kk0 = c0 & 63;
    uint2 hi0, lo0, hi1, lo1;
    split4h(a0, hi0, lo0);
    split4h(a1, hi1, lo1);
    size_t sbase = (size_t)hop * SLOT * 2;
    size_t b0 = sbase + ((size_t)rb * 4 + kc0) * 16384 + SMEM_SWZ((uint32_t)(rloc * 128 + kk0 * 2));
    size_t b1 = sbase + ((size_t)rb * 4 + kc0 + 2) * 16384 + SMEM_SWZ((uint32_t)(rloc * 128 + kk0 * 2));
    *(uint2*)((char*)g_gh + b0) = hi0;  *(uint2*)((char*)g_gl + b0) = lo0;
    *(uint2*)((char*)g_gh + b1) = hi1;  *(uint2*)((char*)g_gl + b1) = lo1;
}

// ---------------- layernorm of decay-weighted hop sum + residual ----------------
__global__ void ln_kernel(const float* __restrict__ acc3,
                          const float* __restrict__ scale,
                          const float* __restrict__ bias,
                          const float* __restrict__ res,
                          float* __restrict__ out, int writeSplit)
{
    int gt = blockIdx.x * blockDim.x + threadIdx.x;
    int n = gt >> 5;
    int lane = gt & 31;
    if (n >= Nn) return;
    const float d1 = 0.60653065971263342f, d2 = 0.36787944117144233f;
    const float* a0p = acc3 + (size_t)n * 256;
    const float* a1p = a0p + (size_t)Nn * 256;
    const float* a2p = a1p + (size_t)Nn * 256;
    float4 v0, v1;
    {
        float4 x0 = *(const float4*)(a0p + lane * 4);
        float4 y0 = *(const float4*)(a1p + lane * 4);
        float4 z0 = *(const float4*)(a2p + lane * 4);
        v0.x = x0.x + d1 * y0.x + d2 * z0.x;
        v0.y = x0.y + d1 * y0.y + d2 * z0.y;
        v0.z = x0.z + d1 * y0.z + d2 * z0.z;
        v0.w = x0.w + d1 * y0.w + d2 * z0.w;
        float4 x1 = *(const float4*)(a0p + 128 + lane * 4);
        float4 y1 = *(const float4*)(a1p + 128 + lane * 4);
        float4 z1 = *(const float4*)(a2p + 128 + lane * 4);
        v1.x = x1.x + d1 * y1.x + d2 * z1.x;
        v1.y = x1.y + d1 * y1.y + d2 * z1.y;
        v1.z = x1.z + d1 * y1.z + d2 * z1.z;
        v1.w = x1.w + d1 * y1.w + d2 * z1.w;
    }
    float sm = v0.x + v0.y + v0.z + v0.w + v1.x + v1.y + v1.z + v1.w;
    float sq = v0.x * v0.x + v0.y * v0.y + v0.z * v0.z + v0.w * v0.w
             + v1.x * v1.x + v1.y * v1.y + v1.z * v1.z + v1.w * v1.w;
#pragma unroll
    for (int o = 16; o > 0; o >>= 1) {
        sm += __shfl_xor_sync(0xffffffffu, sm, o);
        sq += __shfl_xor_sync(0xffffffffu, sq, o);
    }
    float mu = sm * (1.f / 256.f);
    float var = sq * (1.f / 256.f) - mu * mu;
    float rstd = rsqrtf(var + 1e-5f);

    const float* rp = res + (size_t)n * 256;
    float4 r0 = *(const float4*)(rp + lane * 4);
    float4 r1 = *(const float4*)(rp + 128 + lane * 4);
    float4 sc0 = *(const float4*)(scale + lane * 4);
    float4 sc1 = *(const float4*)(scale + 128 + lane * 4);
    float4 b0 = *(const float4*)(bias + lane * 4);
    float4 b1 = *(const float4*)(bias + 128 + lane * 4);

    float4 o0, o1;
    o0.x = (v0.x - mu) * rstd * sc0.x + b0.x + r0.x;
    o0.y = (v0.y - mu) * rstd * sc0.y + b0.y + r0.y;
    o0.z = (v0.z - mu) * rstd * sc0.z + b0.z + r0.z;
    o0.w = (v0.w - mu) * rstd * sc0.w + b0.w + r0.w;
    o1.x = (v1.x - mu) * rstd * sc1.x + b1.x + r1.x;
    o1.y = (v1.y - mu) * rstd * sc1.y + b1.y + r1.y;
    o1.z = (v1.z - mu) * rstd * sc1.z + b1.z + r1.z;
    o1.w = (v1.w - mu) * rstd * sc1.w + b1.w + r1.w;

    float* op = out + (size_t)n * 256;
    *(float4*)(op + lane * 4) = o0;
    *(float4*)(op + 128 + lane * 4) = o1;

    if (writeSplit) {
        int rb = n >> 7, rloc = n & 127;
        int c0 = lane * 4;
        int kc0 = c0 >> 6, kk0 = c0 & 63;
        uint2 hi0, lo0, hi1, lo1;
        split4h(o0, hi0, lo0);
        split4h(o1, hi1, lo1);
        size_t q0 = ((size_t)rb * 4 + kc0) * 16384 + SMEM_SWZ((uint32_t)(rloc * 128 + kk0 * 2));
        size_t q1 = ((size_t)rb * 4 + kc0 + 2) * 16384 + SMEM_SWZ((uint32_t)(rloc * 128 + kk0 * 2));
        *(uint2*)((char*)g_hh + q0) = hi0;  *(uint2*)((char*)g_hl + q0) = lo0;
        *(uint2*)((char*)g_hh + q1) = hi1;  *(uint2*)((char*)g_hl + q1) = lo1;
    }
}

// ---------------- host driver ----------------
extern "C" void kernel_launch(void* const* d_in, const int* in_sizes, int n_in,
                              void* d_out, int out_size)
{
    const float* x        = (const float*)d_in[0];
    const int*   edges    = (const int*)  d_in[1];
    const float* lin1_w   = (const float*)d_in[2];
    const float* lin1_b   = (const float*)d_in[3];
    const float* gat_w    = (const float*)d_in[4];
    const float* att_src  = (const float*)d_in[5];
    const float* att_dst  = (const float*)d_in[6];
    const float* gat_bias = (const float*)d_in[7];
    const float* dec_w    = (const float*)d_in[8];
    const float* dec_b    = (const float*)d_in[9];
    const float* ln_scale = (const float*)d_in[10];
    const float* ln_bias  = (const float*)d_in[11];
    float* out = (float*)d_out;

    cudaFuncSetAttribute(gemm_mma, cudaFuncAttributeMaxDynamicSharedMemorySize, SM_TOTAL);

    float *p_h, *p_h1, *p_acc3, *p_bw;
    __half *p_hh, *p_hl, *p_gh, *p_gl;
    int *p_deg;
    cudaGetSymbolAddress((void**)&p_h,    g_h);
    cudaGetSymbolAddress((void**)&p_h1,   g_h1);
    cudaGetSymbolAddress((void**)&p_acc3, g_acc3);
    cudaGetSymbolAddress((void**)&p_bw,   g_bw);
    cudaGetSymbolAddress((void**)&p_hh,   g_hh);
    cudaGetSymbolAddress((void**)&p_hl,   g_hl);
    cudaGetSymbolAddress((void**)&p_gh,   g_gh);
    cudaGetSymbolAddress((void**)&p_gl,   g_gl);
    cudaGetSymbolAddress((void**)&p_deg,  g_deg);

    // preamble: zero deg, init bw, then one mega prep launch
    cudaMemsetAsync(p_deg, 0, 3 * (size_t)Nn * sizeof(int));
    cudaMemcpyAsync(p_bw, dec_b, 6 * 256 * sizeof(float), cudaMemcpyDeviceToDevice);
    prep_kernel<<<B_PREP, 256>>>(lin1_w, gat_w, dec_w, x, gat_bias, edges);

    bsum3<<<dim3(NB, 3), 256>>>();
    bscan3<<<3, 256>>>();
    rowptr3<<<dim3(NB, 3), 256>>>();
    fill3<<<dim3((Ee + 255) / 256, 3), 256>>>(edges);

    // h = leaky(x @ lin1_w + lin1_b); writes fp32 h + h split
    gemm_mma<<<dim3(NRB, 2), 256, SM_TOTAL>>>(p_gh, p_gl, 0, 0, lin1_b,
                                              nullptr, nullptr, p_h, Nn, 1 | 8, 1.f);

    for (int l = 0; l < 2; l++) {
        // all 3 hop GEMMs: h1[hop] = h @ W[l,hop], fused alphas
        gemm_mma<<<dim3(NRB, 6), 256, SM_TOTAL>>>(p_hh, p_hl, 0, 1 + l * 3, nullptr,
                                                  att_src + (size_t)l * 3 * 256,
                                                  att_dst + (size_t)l * 3 * 256,
                                                  p_h1, Nn, 4, 1.f);
        attn_csr3<<<dim3((Nn * 8 + 255) / 256, 3), 256>>>();
        edge3_csr3<<<dim3((Nn * 32 + 255) / 256, 3), 256>>>();

        // all 3 dec GEMMs: acc3[hop] = leaky(agg[hop] @ dec_w + bw), decay in LN
        gemm_mma<<<dim3(NRB, 6), 256, SM_TOTAL>>>(p_gh, p_gl, 1, 7 + l * 3,
                                                  p_bw + l * 3 * 256,
                                                  nullptr, nullptr,
                                                  p_acc3, Nn, 1 | 16, 1.f);

        ln_kernel<<<(Nn * 32 + 255) / 256, 256>>>(
            p_acc3, ln_scale + (size_t)l * 256, ln_bias + (size_t)l * 256,
            p_h, (l == 0) ? p_h : out, (l == 0) ? 1 : 0);
    }
}

// round 16
// speedup vs baseline: 1.2663x; 1.0633x over previous
#include <cuda_runtime.h>
#include <cuda_fp16.h>
#include <cstdint>
#include <cstddef>

#define Nn 50000
#define Ee 300000
#define DH 256
#define NB 196          // ceil(Nn/256)
#define NRB 391         // ceil(Nn/128) row blocks
#define SLOT ((size_t)NRB * 32768)   // fp16 elements per A-split slot

// prep_kernel block ranges
#define B_CONVW 3328    // 13*65536/256
#define B_CONVA 12500   // Nn*64/256
#define B_HISTH 1172    // ceil(Ee/256)
#define B_HIST  (3 * B_HISTH)
#define B_BIASW 48      // 6 lk * 8 kslices
#define B_PREP  (B_CONVW + B_CONVA + B_HIST + B_BIASW)

// ================= helpers =================
__device__ __forceinline__ uint32_t smem_to_u32(const void* p) {
    uint32_t a;
    asm("{ .reg .u64 t; cvta.to.shared.u64 t, %1; cvt.u32.u64 %0, t; }" : "=r"(a) : "l"(p));
    return a;
}
__device__ __forceinline__ void ldsm4(uint32_t* r, uint32_t addr) {
    asm volatile("ldmatrix.sync.aligned.m8n8.x4.shared.b16 {%0,%1,%2,%3}, [%4];"
        : "=r"(r[0]), "=r"(r[1]), "=r"(r[2]), "=r"(r[3]) : "r"(addr));
}
__device__ __forceinline__ void mma16816h(float* c, const uint32_t* a, const uint32_t* b) {
    asm volatile("mma.sync.aligned.m16n8k16.row.col.f32.f16.f16.f32 "
        "{%0,%1,%2,%3}, {%4,%5,%6,%7}, {%8,%9}, {%0,%1,%2,%3};"
        : "+f"(c[0]), "+f"(c[1]), "+f"(c[2]), "+f"(c[3])
        : "r"(a[0]), "r"(a[1]), "r"(a[2]), "r"(a[3]), "r"(b[0]), "r"(b[1]));
}
#define CP_ASYNC16(sa, gp) \
    asm volatile("cp.async.cg.shared.global [%0], [%1], 16;" :: "r"(sa), "l"(gp))
#define CP_COMMIT() asm volatile("cp.async.commit_group;")
#define CP_WAIT0()  asm volatile("cp.async.wait_group 0;")
#define SMEM_SWZ(o) ((o) ^ ((((uint32_t)(o)) >> 3) & 0x70u))

// fp32x4 -> fp16 hi/lo pairs (hi = RN(v), lo = RN(v - hi))
__device__ __forceinline__ void split4h(float4 v, uint2& hi, uint2& lo) {
    __half2 h0 = __floats2half2_rn(v.x, v.y);
    __half2 h1 = __floats2half2_rn(v.z, v.w);
    __half2 l0 = __floats2half2_rn(v.x - __low2float(h0), v.y - __high2float(h0));
    __half2 l1 = __floats2half2_rn(v.z - __low2float(h1), v.w - __high2float(h1));
    hi.x = *(uint32_t*)&h0;  hi.y = *(uint32_t*)&h1;
    lo.x = *(uint32_t*)&l0;  lo.y = *(uint32_t*)&l1;
}

// ================= scratch (static device globals) =================
__device__ float  g_h   [(size_t)Nn * DH];       // fp32 h (residual path)
__device__ __half g_h1  [3 * (size_t)Nn * DH];   // per-hop GEMM output (fp16, edge gather)
__device__ float  g_acc3[3 * (size_t)Nn * DH];   // per-hop dec output
__device__ float g_as [3 * (size_t)Nn * 8];
__device__ float g_ad [3 * (size_t)Nn * 8];
__device__ float g_s  [3 * (size_t)Nn * 8];
__device__ float g_e  [3 * (size_t)Ee * 8];
__device__ float g_bw [6 * 256];                 // folded dec column bias
// weights: 13 matrices, [4 kc][256 n][64 k] fp16 swizzled (single plane)
__device__ __half g_bh[13 * 65536];
// A splits (fp16 hi/lo): h (1 slot) + x/agg (3 slots, per hop)
__device__ __half g_hh[SLOT];
__device__ __half g_hl[SLOT];
__device__ __half g_gh[3 * SLOT];
__device__ __half g_gl[3 * SLOT];
// CSR (by dst)
__device__ int g_deg [3][Nn];
__device__ int g_rp  [3][Nn];
__device__ int g_csrc[3][Ee];
__device__ int g_cur [3][Nn];
__device__ int g_bsum[3][256];

// ---------------- prep: convw(13) + conva + hist3 + biasw, one launch ----------
__global__ void prep_kernel(const float* __restrict__ lin1_w,
                            const float* __restrict__ gat_w,
                            const float* __restrict__ dec_w,
                            const float* __restrict__ x,
                            const float* __restrict__ gat_bias,
                            const int* __restrict__ edges)
{
    int b = blockIdx.x;
    int tid = threadIdx.x;
    if (b < B_CONVW) {
        int id = b * 256 + tid;
        int g = id >> 16;
        int r = id & 65535;
        int n = r & 255;
        int kf = r >> 8;
        const float* W = (g == 0) ? (lin1_w + r)
                       : (g < 7)  ? (gat_w + (size_t)(g - 1) * 65536 + r)
                                  : (dec_w + (size_t)(g - 7) * 65536 + r);
        float v = *W;
        int kc = kf >> 6, kk = kf & 63;
        uint32_t off = (uint32_t)kc * 32768u + SMEM_SWZ((uint32_t)(n * 128 + kk * 2));
        size_t base = (size_t)g * 131072u;
        *(__half*)((char*)g_bh + base + off) = __float2half(v);
        return;
    }
    b -= B_CONVW;
    if (b < B_CONVA) {
        int id = b * 256 + tid;
        int r = id >> 6, q = id & 63;
        float4 v = *(const float4*)(x + (size_t)r * 256 + q * 4);
        uint2 hi, lo;
        split4h(v, hi, lo);
        int rb = r >> 7, rloc = r & 127;
        int kc = q >> 4, kk = (q & 15) * 4;
        size_t off = ((size_t)rb * 4 + kc) * 16384 + SMEM_SWZ((uint32_t)(rloc * 128 + kk * 2));
        *(uint2*)((char*)g_gh + off) = hi;
        *(uint2*)((char*)g_gl + off) = lo;
        return;
    }
    b -= B_CONVA;
    if (b < B_HIST) {
        int hop = b / B_HISTH;
        int e = (b - hop * B_HISTH) * 256 + tid;
        if (e < Ee) atomicAdd(&g_deg[hop][edges[(size_t)hop * 2 * Ee + Ee + e]], 1);
        return;
    }
    b -= B_HIST;
    {
        int lk = b >> 3;
        int k0 = (b & 7) * 32;
        const float* W = dec_w + (size_t)lk * 65536;
        const float* gb = gat_bias + lk * 256;
        float acc = 0.f;
#pragma unroll
        for (int k = 0; k < 32; k++) acc += gb[k0 + k] * W[(k0 + k) * 256 + tid];
        atomicAdd(&g_bw[lk * 256 + tid], acc);
    }
}

// ---------------- CSR scan chain ----------------
__global__ void bsum3()
{
    __shared__ int ws[8];
    int hop = blockIdx.y;
    int i = blockIdx.x * 256 + threadIdx.x;
    int v = (i < Nn) ? g_deg[hop][i] : 0;
#pragma unroll
    for (int o = 16; o > 0; o >>= 1) v += __shfl_xor_sync(0xffffffffu, v, o);
    if ((threadIdx.x & 31) == 0) ws[threadIdx.x >> 5] = v;
    __syncthreads();
    if (threadIdx.x < 8) {
        int x = ws[threadIdx.x];
#pragma unroll
        for (int o = 4; o > 0; o >>= 1) x += __shfl_xor_sync(0xffu, x, o);
        if (threadIdx.x == 0) g_bsum[hop][blockIdx.x] = x;
    }
}
__global__ void bscan3()
{
    __shared__ int sh[256];
    int hop = blockIdx.x;
    int t = threadIdx.x;
    int orig = (t < NB) ? g_bsum[hop][t] : 0;
    sh[t] = orig;
    __syncthreads();
#pragma unroll
    for (int o = 1; o < 256; o <<= 1) {
        int v = (t >= o) ? sh[t - o] : 0;
        __syncthreads();
        sh[t] += v;
        __syncthreads();
    }
    if (t < NB) g_bsum[hop][t] = sh[t] - orig;
}
__global__ void rowptr3()
{
    __shared__ int sh[256];
    int hop = blockIdx.y;
    int t = threadIdx.x;
    int i = blockIdx.x * 256 + t;
    int d = (i < Nn) ? g_deg[hop][i] : 0;
    sh[t] = d;
    __syncthreads();
#pragma unroll
    for (int o = 1; o < 256; o <<= 1) {
        int v = (t >= o) ? sh[t - o] : 0;
        __syncthreads();
        sh[t] += v;
        __syncthreads();
    }
    if (i < Nn) {
        int rp = g_bsum[hop][blockIdx.x] + sh[t] - d;
        g_rp[hop][i] = rp;
        g_cur[hop][i] = rp;
    }
}
__global__ void fill3(const int* __restrict__ edges)
{
    int hop = blockIdx.y;
    int e = blockIdx.x * blockDim.x + threadIdx.x;
    if (e >= Ee) return;
    const int* src = edges + (size_t)hop * 2 * Ee;
    const int* dst = src + Ee;
    int pos = atomicAdd(&g_cur[hop][dst[e]], 1);
    g_csrc[hop][pos] = src[e];
}

// ---------------- GEMM: fp16 2-pass (Ah+Al)·Bh; B double-buffered ----------
// grid (NRB, 2*nhop): hop = blockIdx.y>>1, colBase = (blockIdx.y&1)*128
// mode bit0: leaky(0.01); bit2: emit alphas; bit3: write h split;
// bit4: per-hop bbias; bit5: C is fp16; A slot per hop when aHop!=0
#define SM_AH 0
#define SM_AL 16384
#define SM_B0 32768
#define SM_B1 49152
#define SM_TOTAL 65536

__global__ void __launch_bounds__(256, 2) gemm_mma(
    const __half* __restrict__ Ah, const __half* __restrict__ Al,
    int aHop, int gidxBase, const float* __restrict__ bbias,
    const float* __restrict__ attS, const float* __restrict__ attD,
    float* __restrict__ C, int M, int mode, float scale)
{
    extern __shared__ char smem[];
    const uint32_t sb = smem_to_u32(smem);
    const int tid = threadIdx.x, wid = tid >> 5, lane = tid & 31;
    const int hop = blockIdx.y >> 1;
    const int rowBase = blockIdx.x * 128;
    const int colBase = (blockIdx.y & 1) * 128;
    const int warpM = (wid & 1) * 64;
    const int warpN = (wid >> 1) * 32;

    const char* bh = (const char*)g_bh + (size_t)(gidxBase + hop) * 131072u + (size_t)colBase * 128u;
    const size_t aoff = (size_t)blockIdx.x * 65536u + (aHop ? (size_t)hop * (SLOT * 2) : 0);
    const char* ah = (const char*)Ah + aoff;
    const char* al = (const char*)Al + aoff;
    __half* C16 = nullptr;
    if (mode & 32) C16 = (__half*)C + (size_t)hop * Nn * 256;
    else           C += (size_t)hop * Nn * 256;
    if (mode & 16) bbias += hop * 256;

    float acc[4][4][4];
#pragma unroll
    for (int i = 0; i < 4; i++)
#pragma unroll
        for (int j = 0; j < 4; j++)
#pragma unroll
            for (int c = 0; c < 4; c++) acc[i][j][c] = 0.f;

    const uint32_t xorA = (uint32_t)((lane & 7) << 4);
    const uint32_t aRow = (uint32_t)(warpM + (lane & 15));
    const uint32_t aSel = (uint32_t)((lane >> 4) << 4);
    const uint32_t bRow4 = (uint32_t)(warpN + (lane & 7) + ((lane >> 4) << 3));
    const uint32_t bSel4 = (uint32_t)(((lane >> 3) & 1) << 4);

    auto cpA = [&](int kc) {
        const char* sah = ah + (size_t)kc * 16384;
        const char* sal = al + (size_t)kc * 16384;
#pragma unroll
        for (int it = 0; it < 4; it++) {
            uint32_t j = (uint32_t)(tid + it * 256) * 16u;
            CP_ASYNC16(sb + SM_AH + j, sah + j);
            CP_ASYNC16(sb + SM_AL + j, sal + j);
        }
    };
    auto cpB = [&](int kc, uint32_t bbase) {
        const char* sbh = bh + (size_t)kc * 32768;
#pragma unroll
        for (int it = 0; it < 4; it++) {
            uint32_t j = (uint32_t)(tid + it * 256) * 16u;
            CP_ASYNC16(sb + bbase + j, sbh + j);
        }
    };

    cpA(0);
    cpB(0, SM_B0);
    CP_COMMIT();
    CP_WAIT0();
    __syncthreads();

    for (int kc = 0; kc < 4; kc++) {
        const uint32_t bbase = (kc & 1) ? SM_B1 : SM_B0;
        if (kc < 3) {
            cpB(kc + 1, bbase ^ (SM_B0 ^ SM_B1));
            CP_COMMIT();
        }
#pragma unroll
        for (int ks = 0; ks < 4; ks++) {
            uint32_t ahf[4][4], alf[4][4], bhf[4][2];
            const uint32_t kOffA = (uint32_t)(ks * 32) + aSel;
            const uint32_t kOffB = (uint32_t)(ks * 32) + bSel4;
#pragma unroll
            for (int i = 0; i < 4; i++) {
                uint32_t off = (((aRow + i * 16) * 128u + kOffA) ^ xorA);
                ldsm4(ahf[i], sb + SM_AH + off);
                ldsm4(alf[i], sb + SM_AL + off);
            }
#pragma unroll
            for (int jp = 0; jp < 2; jp++) {
                uint32_t off = (((bRow4 + jp * 16) * 128u + kOffB) ^ xorA);
                uint32_t rh[4];
                ldsm4(rh, sb + bbase + off);
                bhf[jp * 2][0] = rh[0];     bhf[jp * 2][1] = rh[1];
                bhf[jp * 2 + 1][0] = rh[2]; bhf[jp * 2 + 1][1] = rh[3];
            }
#pragma unroll
            for (int i = 0; i < 4; i++)
#pragma unroll
                for (int j = 0; j < 4; j++) mma16816h(acc[i][j], ahf[i], bhf[j]);
#pragma unroll
            for (int i = 0; i < 4; i++)
#pragma unroll
                for (int j = 0; j < 4; j++) mma16816h(acc[i][j], alf[i], bhf[j]);
        }
        if (kc < 3) {
            __syncthreads();
            cpA(kc + 1);
            CP_COMMIT();
            CP_WAIT0();
            __syncthreads();
        }
    }

    // ---- epilogue ----
    const int tg = lane >> 2;
    const int tc = (lane & 3) * 2;
    const int head = (blockIdx.y & 1) * 4 + (wid >> 1);
#pragma unroll
    for (int i = 0; i < 4; i++) {
        int rloc = warpM + i * 16 + tg;
        int r0 = rowBase + rloc;
        float as0 = 0.f, ad0 = 0.f, as1 = 0.f, ad1 = 0.f;
#pragma unroll
        for (int j = 0; j < 4; j++) {
            int col = colBase + warpN + j * 8 + tc;
            float b0 = bbias ? bbias[col] : 0.f;
            float b1 = bbias ? bbias[col + 1] : 0.f;
            float v0 = acc[i][j][0] + b0, v1 = acc[i][j][1] + b1;
            float v2 = acc[i][j][2] + b0, v3 = acc[i][j][3] + b1;
            if (mode & 1) {
                v0 = (v0 > 0.f) ? v0 : 0.01f * v0;
                v1 = (v1 > 0.f) ? v1 : 0.01f * v1;
                v2 = (v2 > 0.f) ? v2 : 0.01f * v2;
                v3 = (v3 > 0.f) ? v3 : 0.01f * v3;
            }
            v0 *= scale; v1 *= scale; v2 *= scale; v3 *= scale;
            if (mode & 32) {
                if (r0 < M) {
                    __half2 p = __floats2half2_rn(v0, v1);
                    *(__half2*)(C16 + (size_t)r0 * 256 + col) = p;
                }
                if (r0 + 8 < M) {
                    __half2 p = __floats2half2_rn(v2, v3);
                    *(__half2*)(C16 + (size_t)(r0 + 8) * 256 + col) = p;
                }
            } else {
                if (r0 < M)
                    *(float2*)(C + (size_t)r0 * 256 + col) = make_float2(v0, v1);
                if (r0 + 8 < M)
                    *(float2*)(C + (size_t)(r0 + 8) * 256 + col) = make_float2(v2, v3);
            }
            if (mode & 8) {
                int kcq = col >> 6, kk = col & 63;
                size_t tb = ((size_t)blockIdx.x * 4 + kcq) * 16384;
                if (r0 < M) {
                    uint32_t so = SMEM_SWZ((uint32_t)(rloc * 128 + kk * 2));
                    __half2 hp = __floats2half2_rn(v0, v1);
                    __half2 lp = __floats2half2_rn(v0 - __low2float(hp), v1 - __high2float(hp));
                    *(uint32_t*)((char*)g_hh + tb + so) = *(uint32_t*)&hp;
                    *(uint32_t*)((char*)g_hl + tb + so) = *(uint32_t*)&lp;
                }
                if (r0 + 8 < M) {
                    uint32_t so = SMEM_SWZ((uint32_t)((rloc + 8) * 128 + kk * 2));
                    __half2 hp = __floats2half2_rn(v2, v3);
                    __half2 lp = __floats2half2_rn(v2 - __low2float(hp), v3 - __high2float(hp));
                    *(uint32_t*)((char*)g_hh + tb + so) = *(uint32_t*)&hp;
                    *(uint32_t*)((char*)g_hl + tb + so) = *(uint32_t*)&lp;
                }
            }
            if (mode & 4) {
                float s0 = attS[hop * 256 + col], s1 = attS[hop * 256 + col + 1];
                float d0 = attD[hop * 256 + col], d1 = attD[hop * 256 + col + 1];
                as0 += v0 * s0 + v1 * s1;  ad0 += v0 * d0 + v1 * d1;
                as1 += v2 * s0 + v3 * s1;  ad1 += v2 * d0 + v3 * d1;
            }
        }
        if (mode & 4) {
#pragma unroll
            for (int o = 1; o <= 2; o <<= 1) {
                as0 += __shfl_xor_sync(0xffffffffu, as0, o);
                ad0 += __shfl_xor_sync(0xffffffffu, ad0, o);
                as1 += __shfl_xor_sync(0xffffffffu, as1, o);
                ad1 += __shfl_xor_sync(0xffffffffu, ad1, o);
            }
            if ((lane & 3) == 0) {
                size_t ab = (size_t)hop * Nn * 8;
                if (r0 < M)     { g_as[ab + (size_t)r0 * 8 + head] = as0;       g_ad[ab + (size_t)r0 * 8 + head] = ad0; }
                if (r0 + 8 < M) { g_as[ab + (size_t)(r0 + 8) * 8 + head] = as1; g_ad[ab + (size_t)(r0 + 8) * 8 + head] = ad1; }
            }
        }
    }
}

// ---------------- attention softmax (3 hops batched) ----------------
__global__ void attn_csr3()
{
    int t = blockIdx.x * blockDim.x + threadIdx.x;
    if (t >= Nn * 8) return;
    int hop = blockIdx.y;
    int d = t >> 3, h = t & 7;
    int start = g_rp[hop][d];
    int end = start + g_deg[hop][d];
    const float* as = g_as + (size_t)hop * Nn * 8;
    float* ge = g_e + (size_t)hop * Ee * 8;
    float adv = g_ad[(size_t)hop * Nn * 8 + (size_t)d * 8 + h];
    float m = -3.4e38f;
    for (int j = start; j < end; j++) {
        int s = g_csrc[hop][j];
        float lg = as[(size_t)s * 8 + h] + adv;
        lg = (lg > 0.f) ? lg : 0.2f * lg;
        ge[(size_t)j * 8 + h] = lg;
        m = fmaxf(m, lg);
    }
    float sum = 0.f;
    for (int j = start; j < end; j++) {
        float v = __expf(ge[(size_t)j * 8 + h] - m);
        ge[(size_t)j * 8 + h] = v;
        sum += v;
    }
    g_s[(size_t)hop * Nn * 8 + (size_t)d * 8 + h] = sum;
}

// ---------------- aggregate (3 hops batched); h1 fp16 gather; fp16 split out ----
__global__ void edge3_csr3()
{
    int gt = blockIdx.x * blockDim.x + threadIdx.x;
    int d = gt >> 5, lane = gt & 31;
    if (d >= Nn) return;
    int hop = blockIdx.y;
    int start = g_rp[hop][d];
    int end = start + g_deg[hop][d];
    const float* ge = g_e + (size_t)hop * Ee * 8;
    const __half* h1 = g_h1 + (size_t)hop * Nn * 256;
    int h0 = lane >> 3, h1i = 4 + (lane >> 3);
    float i0 = 1.f / (g_s[(size_t)hop * Nn * 8 + (size_t)d * 8 + h0] + 1e-16f);
    float i1 = 1.f / (g_s[(size_t)hop * Nn * 8 + (size_t)d * 8 + h1i] + 1e-16f);
    float4 a0 = make_float4(0.f, 0.f, 0.f, 0.f);
    float4 a1 = a0;
    for (int j = start; j < end; j++) {
        int s = g_csrc[hop][j];
        float al0 = ge[(size_t)j * 8 + h0] * i0;
        float al1 = ge[(size_t)j * 8 + h1i] * i1;
        const __half* hs = h1 + (size_t)s * 256;
        uint2 u0 = *(const uint2*)(hs + lane * 4);          // 4 halves
        uint2 u1 = *(const uint2*)(hs + 128 + lane * 4);
        float2 f00 = __half22float2(*(__half2*)&u0.x);
        float2 f01 = __half22float2(*(__half2*)&u0.y);
        float2 f10 = __half22float2(*(__half2*)&u1.x);
        float2 f11 = __half22float2(*(__half2*)&u1.y);
        a0.x += al0 * f00.x; a0.y += al0 * f00.y; a0.z += al0 * f01.x; a0.w += al0 * f01.y;
        a1.x += al1 * f10.x; a1.y += al1 * f10.y; a1.z += al1 * f11.x; a1.w += al1 * f11.y;
    }
    int rb = d >> 7, rloc = d & 127;
    int c0 = lane * 4;
    int kc0 = c0 >> 6, kk0 = c0 & 63;
    uint2 hi0, lo0, hi1, lo1;
    split4h(a0, hi0, lo0);
    split4h(a1, hi1, lo1);
    size_t sbase = (size_t)hop * SLOT * 2;
    size_t b0 = sbase + ((size_t)rb * 4 + kc0) * 16384 + SMEM_SWZ((uint32_t)(rloc * 128 + kk0 * 2));
    size_t b1 = sbase + ((size_t)rb * 4 + kc0 + 2) * 16384 + SMEM_SWZ((uint32_t)(rloc * 128 + kk0 * 2));
    *(uint2*)((char*)g_gh + b0) = hi0;  *(uint2*)((char*)g_gl + b0) = lo0;
    *(uint2*)((char*)g_gh + b1) = hi1;  *(uint2*)((char*)g_gl + b1) = lo1;
}

// ---------------- layernorm of decay-weighted hop sum + residual ----------------
__global__ void ln_kernel(const float* __restrict__ acc3,
                          const float* __restrict__ scale,
                          const float* __restrict__ bias,
                          const float* __restrict__ res,
                          float* __restrict__ out, int writeSplit)
{
    int gt = blockIdx.x * blockDim.x + threadIdx.x;
    int n = gt >> 5;
    int lane = gt & 31;
    if (n >= Nn) return;
    const float d1 = 0.60653065971263342f, d2 = 0.36787944117144233f;
    const float* a0p = acc3 + (size_t)n * 256;
    const float* a1p = a0p + (size_t)Nn * 256;
    const float* a2p = a1p + (size_t)Nn * 256;
    float4 v0, v1;
    {
        float4 x0 = *(const float4*)(a0p + lane * 4);
        float4 y0 = *(const float4*)(a1p + lane * 4);
        float4 z0 = *(const float4*)(a2p + lane * 4);
        v0.x = x0.x + d1 * y0.x + d2 * z0.x;
        v0.y = x0.y + d1 * y0.y + d2 * z0.y;
        v0.z = x0.z + d1 * y0.z + d2 * z0.z;
        v0.w = x0.w + d1 * y0.w + d2 * z0.w;
        float4 x1 = *(const float4*)(a0p + 128 + lane * 4);
        float4 y1 = *(const float4*)(a1p + 128 + lane * 4);
        float4 z1 = *(const float4*)(a2p + 128 + lane * 4);
        v1.x = x1.x + d1 * y1.x + d2 * z1.x;
        v1.y = x1.y + d1 * y1.y + d2 * z1.y;
        v1.z = x1.z + d1 * y1.z + d2 * z1.z;
        v1.w = x1.w + d1 * y1.w + d2 * z1.w;
    }
    float sm = v0.x + v0.y + v0.z + v0.w + v1.x + v1.y + v1.z + v1.w;
    float sq = v0.x * v0.x + v0.y * v0.y + v0.z * v0.z + v0.w * v0.w
             + v1.x * v1.x + v1.y * v1.y + v1.z * v1.z + v1.w * v1.w;
#pragma unroll
    for (int o = 16; o > 0; o >>= 1) {
        sm += __shfl_xor_sync(0xffffffffu, sm, o);
        sq += __shfl_xor_sync(0xffffffffu, sq, o);
    }
    float mu = sm * (1.f / 256.f);
    float var = sq * (1.f / 256.f) - mu * mu;
    float rstd = rsqrtf(var + 1e-5f);

    const float* rp = res + (size_t)n * 256;
    float4 r0 = *(const float4*)(rp + lane * 4);
    float4 r1 = *(const float4*)(rp + 128 + lane * 4);
    float4 sc0 = *(const float4*)(scale + lane * 4);
    float4 sc1 = *(const float4*)(scale + 128 + lane * 4);
    float4 b0 = *(const float4*)(bias + lane * 4);
    float4 b1 = *(const float4*)(bias + 128 + lane * 4);

    float4 o0, o1;
    o0.x = (v0.x - mu) * rstd * sc0.x + b0.x + r0.x;
    o0.y = (v0.y - mu) * rstd * sc0.y + b0.y + r0.y;
    o0.z = (v0.z - mu) * rstd * sc0.z + b0.z + r0.z;
    o0.w = (v0.w - mu) * rstd * sc0.w + b0.w + r0.w;
    o1.x = (v1.x - mu) * rstd * sc1.x + b1.x + r1.x;
    o1.y = (v1.y - mu) * rstd * sc1.y + b1.y + r1.y;
    o1.z = (v1.z - mu) * rstd * sc1.z + b1.z + r1.z;
    o1.w = (v1.w - mu) * rstd * sc1.w + b1.w + r1.w;

    float* op = out + (size_t)n * 256;
    *(float4*)(op + lane * 4) = o0;
    *(float4*)(op + 128 + lane * 4) = o1;

    if (writeSplit) {
        int rb = n >> 7, rloc = n & 127;
        int c0 = lane * 4;
        int kc0 = c0 >> 6, kk0 = c0 & 63;
        uint2 hi0, lo0, hi1, lo1;
        split4h(o0, hi0, lo0);
        split4h(o1, hi1, lo1);
        size_t q0 = ((size_t)rb * 4 + kc0) * 16384 + SMEM_SWZ((uint32_t)(rloc * 128 + kk0 * 2));
        size_t q1 = ((size_t)rb * 4 + kc0 + 2) * 16384 + SMEM_SWZ((uint32_t)(rloc * 128 + kk0 * 2));
        *(uint2*)((char*)g_hh + q0) = hi0;  *(uint2*)((char*)g_hl + q0) = lo0;
        *(uint2*)((char*)g_hh + q1) = hi1;  *(uint2*)((char*)g_hl + q1) = lo1;
    }
}

// ---------------- host driver ----------------
extern "C" void kernel_launch(void* const* d_in, const int* in_sizes, int n_in,
                              void* d_out, int out_size)
{
    const float* x        = (const float*)d_in[0];
    const int*   edges    = (const int*)  d_in[1];
    const float* lin1_w   = (const float*)d_in[2];
    const float* lin1_b   = (const float*)d_in[3];
    const float* gat_w    = (const float*)d_in[4];
    const float* att_src  = (const float*)d_in[5];
    const float* att_dst  = (const float*)d_in[6];
    const float* gat_bias = (const float*)d_in[7];
    const float* dec_w    = (const float*)d_in[8];
    const float* dec_b    = (const float*)d_in[9];
    const float* ln_scale = (const float*)d_in[10];
    const float* ln_bias  = (const float*)d_in[11];
    float* out = (float*)d_out;

    cudaFuncSetAttribute(gemm_mma, cudaFuncAttributeMaxDynamicSharedMemorySize, SM_TOTAL);

    float *p_h, *p_acc3, *p_bw;
    __half *p_h1, *p_hh, *p_hl, *p_gh, *p_gl;
    int *p_deg;
    cudaGetSymbolAddress((void**)&p_h,    g_h);
    cudaGetSymbolAddress((void**)&p_h1,   g_h1);
    cudaGetSymbolAddress((void**)&p_acc3, g_acc3);
    cudaGetSymbolAddress((void**)&p_bw,   g_bw);
    cudaGetSymbolAddress((void**)&p_hh,   g_hh);
    cudaGetSymbolAddress((void**)&p_hl,   g_hl);
    cudaGetSymbolAddress((void**)&p_gh,   g_gh);
    cudaGetSymbolAddress((void**)&p_gl,   g_gl);
    cudaGetSymbolAddress((void**)&p_deg,  g_deg);

    // preamble
    cudaMemsetAsync(p_deg, 0, 3 * (size_t)Nn * sizeof(int));
    cudaMemcpyAsync(p_bw, dec_b, 6 * 256 * sizeof(float), cudaMemcpyDeviceToDevice);
    prep_kernel<<<B_PREP, 256>>>(lin1_w, gat_w, dec_w, x, gat_bias, edges);

    bsum3<<<dim3(NB, 3), 256>>>();
    bscan3<<<3, 256>>>();
    rowptr3<<<dim3(NB, 3), 256>>>();
    fill3<<<dim3((Ee + 255) / 256, 3), 256>>>(edges);

    // h = leaky(x @ lin1_w + lin1_b); writes fp32 h + h split
    gemm_mma<<<dim3(NRB, 2), 256, SM_TOTAL>>>(p_gh, p_gl, 0, 0, lin1_b,
                                              nullptr, nullptr, p_h, Nn, 1 | 8, 1.f);

    for (int l = 0; l < 2; l++) {
        // all 3 hop GEMMs: h1[hop] (fp16) = h @ W[l,hop], fused alphas
        gemm_mma<<<dim3(NRB, 6), 256, SM_TOTAL>>>(p_hh, p_hl, 0, 1 + l * 3, nullptr,
                                                  att_src + (size_t)l * 3 * 256,
                                                  att_dst + (size_t)l * 3 * 256,
                                                  (float*)p_h1, Nn, 4 | 32, 1.f);
        attn_csr3<<<dim3((Nn * 8 + 255) / 256, 3), 256>>>();
        edge3_csr3<<<dim3((Nn * 32 + 255) / 256, 3), 256>>>();

        // all 3 dec GEMMs: acc3[hop] = leaky(agg[hop] @ dec_w + bw), decay in LN
        gemm_mma<<<dim3(NRB, 6), 256, SM_TOTAL>>>(p_gh, p_gl, 1, 7 + l * 3,
                                                  p_bw + l * 3 * 256,
                                                  nullptr, nullptr,
                                                  p_acc3, Nn, 1 | 16, 1.f);

        ln_kernel<<<(Nn * 32 + 255) / 256, 256>>>(
            p_acc3, ln_scale + (size_t)l * 256, ln_bias + (size_t)l * 256,
            p_h, (l == 0) ? p_h : out, (l == 0) ? 1 : 0);
    }
}

// round 17
// speedup vs baseline: 1.3680x; 1.0803x over previous
#include <cuda_runtime.h>
#include <cuda_fp16.h>
#include <cstdint>
#include <cstddef>

#define Nn 50000
#define Ee 300000
#define DH 256
#define NB 196          // ceil(Nn/256)
#define NRB 391         // ceil(Nn/128) row blocks
#define SLOT ((size_t)NRB * 32768)   // fp16 elements per A-split slot

// prep_kernel block ranges
#define B_CONVW 3328    // 13*65536/256
#define B_CONVA 12500   // Nn*64/256
#define B_HISTH 1172    // ceil(Ee/256)
#define B_HIST  (3 * B_HISTH)
#define B_BIASW 48      // 6 lk * 8 kslices
#define B_PREP  (B_CONVW + B_CONVA + B_HIST + B_BIASW)

// ================= helpers =================
__device__ __forceinline__ uint32_t smem_to_u32(const void* p) {
    uint32_t a;
    asm("{ .reg .u64 t; cvta.to.shared.u64 t, %1; cvt.u32.u64 %0, t; }" : "=r"(a) : "l"(p));
    return a;
}
__device__ __forceinline__ void ldsm4(uint32_t* r, uint32_t addr) {
    asm volatile("ldmatrix.sync.aligned.m8n8.x4.shared.b16 {%0,%1,%2,%3}, [%4];"
        : "=r"(r[0]), "=r"(r[1]), "=r"(r[2]), "=r"(r[3]) : "r"(addr));
}
__device__ __forceinline__ void mma16816h(float* c, const uint32_t* a, const uint32_t* b) {
    asm volatile("mma.sync.aligned.m16n8k16.row.col.f32.f16.f16.f32 "
        "{%0,%1,%2,%3}, {%4,%5,%6,%7}, {%8,%9}, {%0,%1,%2,%3};"
        : "+f"(c[0]), "+f"(c[1]), "+f"(c[2]), "+f"(c[3])
        : "r"(a[0]), "r"(a[1]), "r"(a[2]), "r"(a[3]), "r"(b[0]), "r"(b[1]));
}
#define CP_ASYNC16(sa, gp) \
    asm volatile("cp.async.cg.shared.global [%0], [%1], 16;" :: "r"(sa), "l"(gp))
#define CP_COMMIT() asm volatile("cp.async.commit_group;")
#define CP_WAIT0()  asm volatile("cp.async.wait_group 0;")
#define SMEM_SWZ(o) ((o) ^ ((((uint32_t)(o)) >> 3) & 0x70u))

// fp32x4 -> fp16 hi/lo pairs (hi = RN(v), lo = RN(v - hi))
__device__ __forceinline__ void split4h(float4 v, uint2& hi, uint2& lo) {
    __half2 h0 = __floats2half2_rn(v.x, v.y);
    __half2 h1 = __floats2half2_rn(v.z, v.w);
    __half2 l0 = __floats2half2_rn(v.x - __low2float(h0), v.y - __high2float(h0));
    __half2 l1 = __floats2half2_rn(v.z - __low2float(h1), v.w - __high2float(h1));
    hi.x = *(uint32_t*)&h0;  hi.y = *(uint32_t*)&h1;
    lo.x = *(uint32_t*)&l0;  lo.y = *(uint32_t*)&l1;
}

// ================= scratch (static device globals) =================
__device__ float  g_h   [(size_t)Nn * DH];       // fp32 h (residual path)
__device__ __half g_h1  [3 * (size_t)Nn * DH];   // per-hop GEMM output (fp16, edge gather)
__device__ float  g_acc3[3 * (size_t)Nn * DH];   // per-hop dec output
__device__ float g_as [3 * (size_t)Nn * 8];
__device__ float g_ad [3 * (size_t)Nn * 8];
__device__ float g_s  [3 * (size_t)Nn * 8];
__device__ float g_e  [3 * (size_t)Ee * 8];
__device__ float g_bw [6 * 256];                 // folded dec column bias
// weights: 13 matrices, [4 kc][256 n][64 k] fp16 swizzled (single plane)
__device__ __half g_bh[13 * 65536];
// A splits (fp16 hi/lo): h (1 slot) + x/agg (3 slots, per hop; agg uses hi only)
__device__ __half g_hh[SLOT];
__device__ __half g_hl[SLOT];
__device__ __half g_gh[3 * SLOT];
__device__ __half g_gl[3 * SLOT];
// CSR (by dst)
__device__ int g_deg [3][Nn];
__device__ int g_rp  [3][Nn];
__device__ int g_csrc[3][Ee];
__device__ int g_cur [3][Nn];
__device__ int g_bsum[3][256];

// ---------------- prep: convw(13) + conva + hist3 + biasw, one launch ----------
__global__ void prep_kernel(const float* __restrict__ lin1_w,
                            const float* __restrict__ gat_w,
                            const float* __restrict__ dec_w,
                            const float* __restrict__ x,
                            const float* __restrict__ gat_bias,
                            const int* __restrict__ edges)
{
    int b = blockIdx.x;
    int tid = threadIdx.x;
    if (b < B_CONVW) {
        int id = b * 256 + tid;
        int g = id >> 16;
        int r = id & 65535;
        int n = r & 255;
        int kf = r >> 8;
        const float* W = (g == 0) ? (lin1_w + r)
                       : (g < 7)  ? (gat_w + (size_t)(g - 1) * 65536 + r)
                                  : (dec_w + (size_t)(g - 7) * 65536 + r);
        float v = *W;
        int kc = kf >> 6, kk = kf & 63;
        uint32_t off = (uint32_t)kc * 32768u + SMEM_SWZ((uint32_t)(n * 128 + kk * 2));
        size_t base = (size_t)g * 131072u;
        *(__half*)((char*)g_bh + base + off) = __float2half(v);
        return;
    }
    b -= B_CONVW;
    if (b < B_CONVA) {
        int id = b * 256 + tid;
        int r = id >> 6, q = id & 63;
        float4 v = *(const float4*)(x + (size_t)r * 256 + q * 4);
        uint2 hi, lo;
        split4h(v, hi, lo);
        int rb = r >> 7, rloc = r & 127;
        int kc = q >> 4, kk = (q & 15) * 4;
        size_t off = ((size_t)rb * 4 + kc) * 16384 + SMEM_SWZ((uint32_t)(rloc * 128 + kk * 2));
        *(uint2*)((char*)g_gh + off) = hi;
        *(uint2*)((char*)g_gl + off) = lo;
        return;
    }
    b -= B_CONVA;
    if (b < B_HIST) {
        int hop = b / B_HISTH;
        int e = (b - hop * B_HISTH) * 256 + tid;
        if (e < Ee) atomicAdd(&g_deg[hop][edges[(size_t)hop * 2 * Ee + Ee + e]], 1);
        return;
    }
    b -= B_HIST;
    {
        int lk = b >> 3;
        int k0 = (b & 7) * 32;
        const float* W = dec_w + (size_t)lk * 65536;
        const float* gb = gat_bias + lk * 256;
        float acc = 0.f;
#pragma unroll
        for (int k = 0; k < 32; k++) acc += gb[k0 + k] * W[(k0 + k) * 256 + tid];
        atomicAdd(&g_bw[lk * 256 + tid], acc);
    }
}

// ---------------- CSR scan chain ----------------
__global__ void bsum3()
{
    __shared__ int ws[8];
    int hop = blockIdx.y;
    int i = blockIdx.x * 256 + threadIdx.x;
    int v = (i < Nn) ? g_deg[hop][i] : 0;
#pragma unroll
    for (int o = 16; o > 0; o >>= 1) v += __shfl_xor_sync(0xffffffffu, v, o);
    if ((threadIdx.x & 31) == 0) ws[threadIdx.x >> 5] = v;
    __syncthreads();
    if (threadIdx.x < 8) {
        int x = ws[threadIdx.x];
#pragma unroll
        for (int o = 4; o > 0; o >>= 1) x += __shfl_xor_sync(0xffu, x, o);
        if (threadIdx.x == 0) g_bsum[hop][blockIdx.x] = x;
    }
}
__global__ void bscan3()
{
    __shared__ int sh[256];
    int hop = blockIdx.x;
    int t = threadIdx.x;
    int orig = (t < NB) ? g_bsum[hop][t] : 0;
    sh[t] = orig;
    __syncthreads();
#pragma unroll
    for (int o = 1; o < 256; o <<= 1) {
        int v = (t >= o) ? sh[t - o] : 0;
        __syncthreads();
        sh[t] += v;
        __syncthreads();
    }
    if (t < NB) g_bsum[hop][t] = sh[t] - orig;
}
__global__ void rowptr3()
{
    __shared__ int sh[256];
    int hop = blockIdx.y;
    int t = threadIdx.x;
    int i = blockIdx.x * 256 + t;
    int d = (i < Nn) ? g_deg[hop][i] : 0;
    sh[t] = d;
    __syncthreads();
#pragma unroll
    for (int o = 1; o < 256; o <<= 1) {
        int v = (t >= o) ? sh[t - o] : 0;
        __syncthreads();
        sh[t] += v;
        __syncthreads();
    }
    if (i < Nn) {
        int rp = g_bsum[hop][blockIdx.x] + sh[t] - d;
        g_rp[hop][i] = rp;
        g_cur[hop][i] = rp;
    }
}
__global__ void fill3(const int* __restrict__ edges)
{
    int hop = blockIdx.y;
    int e = blockIdx.x * blockDim.x + threadIdx.x;
    if (e >= Ee) return;
    const int* src = edges + (size_t)hop * 2 * Ee;
    const int* dst = src + Ee;
    int pos = atomicAdd(&g_cur[hop][dst[e]], 1);
    g_csrc[hop][pos] = src[e];
}

// ---------------- GEMM: fp16 (Ah[+Al])·Bh; B double-buffered ----------
// grid (NRB, 2*nhop): hop = blockIdx.y>>1, colBase = (blockIdx.y&1)*128
// mode bit0: leaky(0.01); bit2: emit alphas; bit3: write h split;
// bit4: per-hop bbias; bit5: C fp16; bit6: single-pass A (hi only)
#define SM_AH 0
#define SM_AL 16384
#define SM_B0 32768
#define SM_B1 49152
#define SM_TOTAL 65536

__global__ void __launch_bounds__(256, 2) gemm_mma(
    const __half* __restrict__ Ah, const __half* __restrict__ Al,
    int aHop, int gidxBase, const float* __restrict__ bbias,
    const float* __restrict__ attS, const float* __restrict__ attD,
    float* __restrict__ C, int M, int mode, float scale)
{
    extern __shared__ char smem[];
    const uint32_t sb = smem_to_u32(smem);
    const int tid = threadIdx.x, wid = tid >> 5, lane = tid & 31;
    const int hop = blockIdx.y >> 1;
    const int rowBase = blockIdx.x * 128;
    const int colBase = (blockIdx.y & 1) * 128;
    const int warpM = (wid & 1) * 64;
    const int warpN = (wid >> 1) * 32;
    const bool onePass = (mode & 64) != 0;

    const char* bh = (const char*)g_bh + (size_t)(gidxBase + hop) * 131072u + (size_t)colBase * 128u;
    const size_t aoff = (size_t)blockIdx.x * 65536u + (aHop ? (size_t)hop * (SLOT * 2) : 0);
    const char* ah = (const char*)Ah + aoff;
    const char* al = (const char*)Al + aoff;
    __half* C16 = nullptr;
    if (mode & 32) C16 = (__half*)C + (size_t)hop * Nn * 256;
    else           C += (size_t)hop * Nn * 256;
    if (mode & 16) bbias += hop * 256;

    float acc[4][4][4];
#pragma unroll
    for (int i = 0; i < 4; i++)
#pragma unroll
        for (int j = 0; j < 4; j++)
#pragma unroll
            for (int c = 0; c < 4; c++) acc[i][j][c] = 0.f;

    const uint32_t xorA = (uint32_t)((lane & 7) << 4);
    const uint32_t aRow = (uint32_t)(warpM + (lane & 15));
    const uint32_t aSel = (uint32_t)((lane >> 4) << 4);
    const uint32_t bRow4 = (uint32_t)(warpN + (lane & 7) + ((lane >> 4) << 3));
    const uint32_t bSel4 = (uint32_t)(((lane >> 3) & 1) << 4);

    auto cpA = [&](int kc) {
        const char* sah = ah + (size_t)kc * 16384;
        const char* sal = al + (size_t)kc * 16384;
#pragma unroll
        for (int it = 0; it < 4; it++) {
            uint32_t j = (uint32_t)(tid + it * 256) * 16u;
            CP_ASYNC16(sb + SM_AH + j, sah + j);
            if (!onePass) CP_ASYNC16(sb + SM_AL + j, sal + j);
        }
    };
    auto cpB = [&](int kc, uint32_t bbase) {
        const char* sbh = bh + (size_t)kc * 32768;
#pragma unroll
        for (int it = 0; it < 4; it++) {
            uint32_t j = (uint32_t)(tid + it * 256) * 16u;
            CP_ASYNC16(sb + bbase + j, sbh + j);
        }
    };

    cpA(0);
    cpB(0, SM_B0);
    CP_COMMIT();
    CP_WAIT0();
    __syncthreads();

    for (int kc = 0; kc < 4; kc++) {
        const uint32_t bbase = (kc & 1) ? SM_B1 : SM_B0;
        if (kc < 3) {
            cpB(kc + 1, bbase ^ (SM_B0 ^ SM_B1));
            CP_COMMIT();
        }
#pragma unroll
        for (int ks = 0; ks < 4; ks++) {
            uint32_t ahf[4][4], alf[4][4], bhf[4][2];
            const uint32_t kOffA = (uint32_t)(ks * 32) + aSel;
            const uint32_t kOffB = (uint32_t)(ks * 32) + bSel4;
#pragma unroll
            for (int i = 0; i < 4; i++) {
                uint32_t off = (((aRow + i * 16) * 128u + kOffA) ^ xorA);
                ldsm4(ahf[i], sb + SM_AH + off);
            }
            if (!onePass) {
#pragma unroll
                for (int i = 0; i < 4; i++) {
                    uint32_t off = (((aRow + i * 16) * 128u + kOffA) ^ xorA);
                    ldsm4(alf[i], sb + SM_AL + off);
                }
            }
#pragma unroll
            for (int jp = 0; jp < 2; jp++) {
                uint32_t off = (((bRow4 + jp * 16) * 128u + kOffB) ^ xorA);
                uint32_t rh[4];
                ldsm4(rh, sb + bbase + off);
                bhf[jp * 2][0] = rh[0];     bhf[jp * 2][1] = rh[1];
                bhf[jp * 2 + 1][0] = rh[2]; bhf[jp * 2 + 1][1] = rh[3];
            }
#pragma unroll
            for (int i = 0; i < 4; i++)
#pragma unroll
                for (int j = 0; j < 4; j++) mma16816h(acc[i][j], ahf[i], bhf[j]);
            if (!onePass) {
#pragma unroll
                for (int i = 0; i < 4; i++)
#pragma unroll
                    for (int j = 0; j < 4; j++) mma16816h(acc[i][j], alf[i], bhf[j]);
            }
        }
        if (kc < 3) {
            __syncthreads();
            cpA(kc + 1);
            CP_COMMIT();
            CP_WAIT0();
            __syncthreads();
        }
    }

    // ---- epilogue ----
    const int tg = lane >> 2;
    const int tc = (lane & 3) * 2;
    const int head = (blockIdx.y & 1) * 4 + (wid >> 1);
#pragma unroll
    for (int i = 0; i < 4; i++) {
        int rloc = warpM + i * 16 + tg;
        int r0 = rowBase + rloc;
        float as0 = 0.f, ad0 = 0.f, as1 = 0.f, ad1 = 0.f;
#pragma unroll
        for (int j = 0; j < 4; j++) {
            int col = colBase + warpN + j * 8 + tc;
            float b0 = bbias ? bbias[col] : 0.f;
            float b1 = bbias ? bbias[col + 1] : 0.f;
            float v0 = acc[i][j][0] + b0, v1 = acc[i][j][1] + b1;
            float v2 = acc[i][j][2] + b0, v3 = acc[i][j][3] + b1;
            if (mode & 1) {
                v0 = (v0 > 0.f) ? v0 : 0.01f * v0;
                v1 = (v1 > 0.f) ? v1 : 0.01f * v1;
                v2 = (v2 > 0.f) ? v2 : 0.01f * v2;
                v3 = (v3 > 0.f) ? v3 : 0.01f * v3;
            }
            v0 *= scale; v1 *= scale; v2 *= scale; v3 *= scale;
            if (mode & 32) {
                if (r0 < M) {
                    __half2 p = __floats2half2_rn(v0, v1);
                    *(__half2*)(C16 + (size_t)r0 * 256 + col) = p;
                }
                if (r0 + 8 < M) {
                    __half2 p = __floats2half2_rn(v2, v3);
                    *(__half2*)(C16 + (size_t)(r0 + 8) * 256 + col) = p;
                }
            } else {
                if (r0 < M)
                    *(float2*)(C + (size_t)r0 * 256 + col) = make_float2(v0, v1);
                if (r0 + 8 < M)
                    *(float2*)(C + (size_t)(r0 + 8) * 256 + col) = make_float2(v2, v3);
            }
            if (mode & 8) {
                int kcq = col >> 6, kk = col & 63;
                size_t tb = ((size_t)blockIdx.x * 4 + kcq) * 16384;
                if (r0 < M) {
                    uint32_t so = SMEM_SWZ((uint32_t)(rloc * 128 + kk * 2));
                    __half2 hp = __floats2half2_rn(v0, v1);
                    __half2 lp = __floats2half2_rn(v0 - __low2float(hp), v1 - __high2float(hp));
                    *(uint32_t*)((char*)g_hh + tb + so) = *(uint32_t*)&hp;
                    *(uint32_t*)((char*)g_hl + tb + so) = *(uint32_t*)&lp;
                }
                if (r0 + 8 < M) {
                    uint32_t so = SMEM_SWZ((uint32_t)((rloc + 8) * 128 + kk * 2));
                    __half2 hp = __floats2half2_rn(v2, v3);
                    __half2 lp = __floats2half2_rn(v2 - __low2float(hp), v3 - __high2float(hp));
                    *(uint32_t*)((char*)g_hh + tb + so) = *(uint32_t*)&hp;
                    *(uint32_t*)((char*)g_hl + tb + so) = *(uint32_t*)&lp;
                }
            }
            if (mode & 4) {
                float s0 = attS[hop * 256 + col], s1 = attS[hop * 256 + col + 1];
                float d0 = attD[hop * 256 + col], d1 = attD[hop * 256 + col + 1];
                as0 += v0 * s0 + v1 * s1;  ad0 += v0 * d0 + v1 * d1;
                as1 += v2 * s0 + v3 * s1;  ad1 += v2 * d0 + v3 * d1;
            }
        }
        if (mode & 4) {
#pragma unroll
            for (int o = 1; o <= 2; o <<= 1) {
                as0 += __shfl_xor_sync(0xffffffffu, as0, o);
                ad0 += __shfl_xor_sync(0xffffffffu, ad0, o);
                as1 += __shfl_xor_sync(0xffffffffu, as1, o);
                ad1 += __shfl_xor_sync(0xffffffffu, ad1, o);
            }
            if ((lane & 3) == 0) {
                size_t ab = (size_t)hop * Nn * 8;
                if (r0 < M)     { g_as[ab + (size_t)r0 * 8 + head] = as0;       g_ad[ab + (size_t)r0 * 8 + head] = ad0; }
                if (r0 + 8 < M) { g_as[ab + (size_t)(r0 + 8) * 8 + head] = as1; g_ad[ab + (size_t)(r0 + 8) * 8 + head] = ad1; }
            }
        }
    }
}

// ---------------- attention softmax (3 hops batched) ----------------
__global__ void attn_csr3()
{
    int t = blockIdx.x * blockDim.x + threadIdx.x;
    if (t >= Nn * 8) return;
    int hop = blockIdx.y;
    int d = t >> 3, h = t & 7;
    int start = g_rp[hop][d];
    int end = start + g_deg[hop][d];
    const float* as = g_as + (size_t)hop * Nn * 8;
    float* ge = g_e + (size_t)hop * Ee * 8;
    float adv = g_ad[(size_t)hop * Nn * 8 + (size_t)d * 8 + h];
    float m = -3.4e38f;
    for (int j = start; j < end; j++) {
        int s = g_csrc[hop][j];
        float lg = as[(size_t)s * 8 + h] + adv;
        lg = (lg > 0.f) ? lg : 0.2f * lg;
        ge[(size_t)j * 8 + h] = lg;
        m = fmaxf(m, lg);
    }
    float sum = 0.f;
    for (int j = start; j < end; j++) {
        float v = __expf(ge[(size_t)j * 8 + h] - m);
        ge[(size_t)j * 8 + h] = v;
        sum += v;
    }
    g_s[(size_t)hop * Nn * 8 + (size_t)d * 8 + h] = sum;
}

// ---------------- aggregate; h1 fp16 gather; plain fp16 agg out -----------------
__global__ void edge3_csr3()
{
    int gt = blockIdx.x * blockDim.x + threadIdx.x;
    int d = gt >> 5, lane = gt & 31;
    if (d >= Nn) return;
    int hop = blockIdx.y;
    int start = g_rp[hop][d];
    int end = start + g_deg[hop][d];
    const float* ge = g_e + (size_t)hop * Ee * 8;
    const __half* h1 = g_h1 + (size_t)hop * Nn * 256;
    int h0 = lane >> 3, h1i = 4 + (lane >> 3);
    float i0 = 1.f / (g_s[(size_t)hop * Nn * 8 + (size_t)d * 8 + h0] + 1e-16f);
    float i1 = 1.f / (g_s[(size_t)hop * Nn * 8 + (size_t)d * 8 + h1i] + 1e-16f);
    float4 a0 = make_float4(0.f, 0.f, 0.f, 0.f);
    float4 a1 = a0;
    for (int j = start; j < end; j++) {
        int s = g_csrc[hop][j];
        float al0 = ge[(size_t)j * 8 + h0] * i0;
        float al1 = ge[(size_t)j * 8 + h1i] * i1;
        const __half* hs = h1 + (size_t)s * 256;
        uint2 u0 = *(const uint2*)(hs + lane * 4);
        uint2 u1 = *(const uint2*)(hs + 128 + lane * 4);
        float2 f00 = __half22float2(*(__half2*)&u0.x);
        float2 f01 = __half22float2(*(__half2*)&u0.y);
        float2 f10 = __half22float2(*(__half2*)&u1.x);
        float2 f11 = __half22float2(*(__half2*)&u1.y);
        a0.x += al0 * f00.x; a0.y += al0 * f00.y; a0.z += al0 * f01.x; a0.w += al0 * f01.y;
        a1.x += al1 * f10.x; a1.y += al1 * f10.y; a1.z += al1 * f11.x; a1.w += al1 * f11.y;
    }
    int rb = d >> 7, rloc = d & 127;
    int c0 = lane * 4;
    int kc0 = c0 >> 6, kk0 = c0 & 63;
    __half2 p00 = __floats2half2_rn(a0.x, a0.y);
    __half2 p01 = __floats2half2_rn(a0.z, a0.w);
    __half2 p10 = __floats2half2_rn(a1.x, a1.y);
    __half2 p11 = __floats2half2_rn(a1.z, a1.w);
    uint2 hi0, hi1;
    hi0.x = *(uint32_t*)&p00;  hi0.y = *(uint32_t*)&p01;
    hi1.x = *(uint32_t*)&p10;  hi1.y = *(uint32_t*)&p11;
    size_t sbase = (size_t)hop * SLOT * 2;
    size_t b0 = sbase + ((size_t)rb * 4 + kc0) * 16384 + SMEM_SWZ((uint32_t)(rloc * 128 + kk0 * 2));
    size_t b1 = sbase + ((size_t)rb * 4 + kc0 + 2) * 16384 + SMEM_SWZ((uint32_t)(rloc * 128 + kk0 * 2));
    *(uint2*)((char*)g_gh + b0) = hi0;
    *(uint2*)((char*)g_gh + b1) = hi1;
}

// ---------------- layernorm of decay-weighted hop sum + residual ----------------
__global__ void ln_kernel(const float* __restrict__ acc3,
                          const float* __restrict__ scale,
                          const float* __restrict__ bias,
                          const float* __restrict__ res,
                          float* __restrict__ out, int writeSplit)
{
    int gt = blockIdx.x * blockDim.x + threadIdx.x;
    int n = gt >> 5;
    int lane = gt & 31;
    if (n >= Nn) return;
    const float d1 = 0.60653065971263342f, d2 = 0.36787944117144233f;
    const float* a0p = acc3 + (size_t)n * 256;
    const float* a1p = a0p + (size_t)Nn * 256;
    const float* a2p = a1p + (size_t)Nn * 256;
    float4 v0, v1;
    {
        float4 x0 = *(const float4*)(a0p + lane * 4);
        float4 y0 = *(const float4*)(a1p + lane * 4);
        float4 z0 = *(const float4*)(a2p + lane * 4);
        v0.x = x0.x + d1 * y0.x + d2 * z0.x;
        v0.y = x0.y + d1 * y0.y + d2 * z0.y;
        v0.z = x0.z + d1 * y0.z + d2 * z0.z;
        v0.w = x0.w + d1 * y0.w + d2 * z0.w;
        float4 x1 = *(const float4*)(a0p + 128 + lane * 4);
        float4 y1 = *(const float4*)(a1p + 128 + lane * 4);
        float4 z1 = *(const float4*)(a2p + 128 + lane * 4);
        v1.x = x1.x + d1 * y1.x + d2 * z1.x;
        v1.y = x1.y + d1 * y1.y + d2 * z1.y;
        v1.z = x1.z + d1 * y1.z + d2 * z1.z;
        v1.w = x1.w + d1 * y1.w + d2 * z1.w;
    }
    float sm = v0.x + v0.y + v0.z + v0.w + v1.x + v1.y + v1.z + v1.w;
    float sq = v0.x * v0.x + v0.y * v0.y + v0.z * v0.z + v0.w * v0.w
             + v1.x * v1.x + v1.y * v1.y + v1.z * v1.z + v1.w * v1.w;
#pragma unroll
    for (int o = 16; o > 0; o >>= 1) {
        sm += __shfl_xor_sync(0xffffffffu, sm, o);
        sq += __shfl_xor_sync(0xffffffffu, sq, o);
    }
    float mu = sm * (1.f / 256.f);
    float var = sq * (1.f / 256.f) - mu * mu;
    float rstd = rsqrtf(var + 1e-5f);

    const float* rp = res + (size_t)n * 256;
    float4 r0 = *(const float4*)(rp + lane * 4);
    float4 r1 = *(const float4*)(rp + 128 + lane * 4);
    float4 sc0 = *(const float4*)(scale + lane * 4);
    float4 sc1 = *(const float4*)(scale + 128 + lane * 4);
    float4 b0 = *(const float4*)(bias + lane * 4);
    float4 b1 = *(const float4*)(bias + 128 + lane * 4);

    float4 o0, o1;
    o0.x = (v0.x - mu) * rstd * sc0.x + b0.x + r0.x;
    o0.y = (v0.y - mu) * rstd * sc0.y + b0.y + r0.y;
    o0.z = (v0.z - mu) * rstd * sc0.z + b0.z + r0.z;
    o0.w = (v0.w - mu) * rstd * sc0.w + b0.w + r0.w;
    o1.x = (v1.x - mu) * rstd * sc1.x + b1.x + r1.x;
    o1.y = (v1.y - mu) * rstd * sc1.y + b1.y + r1.y;
    o1.z = (v1.z - mu) * rstd * sc1.z + b1.z + r1.z;
    o1.w = (v1.w - mu) * rstd * sc1.w + b1.w + r1.w;

    float* op = out + (size_t)n * 256;
    *(float4*)(op + lane * 4) = o0;
    *(float4*)(op + 128 + lane * 4) = o1;

    if (writeSplit) {
        int rb = n >> 7, rloc = n & 127;
        int c0 = lane * 4;
        int kc0 = c0 >> 6, kk0 = c0 & 63;
        uint2 hi0, lo0, hi1, lo1;
        split4h(o0, hi0, lo0);
        split4h(o1, hi1, lo1);
        size_t q0 = ((size_t)rb * 4 + kc0) * 16384 + SMEM_SWZ((uint32_t)(rloc * 128 + kk0 * 2));
        size_t q1 = ((size_t)rb * 4 + kc0 + 2) * 16384 + SMEM_SWZ((uint32_t)(rloc * 128 + kk0 * 2));
        *(uint2*)((char*)g_hh + q0) = hi0;  *(uint2*)((char*)g_hl + q0) = lo0;
        *(uint2*)((char*)g_hh + q1) = hi1;  *(uint2*)((char*)g_hl + q1) = lo1;
    }
}

// ---------------- host driver ----------------
extern "C" void kernel_launch(void* const* d_in, const int* in_sizes, int n_in,
                              void* d_out, int out_size)
{
    const float* x        = (const float*)d_in[0];
    const int*   edges    = (const int*)  d_in[1];
    const float* lin1_w   = (const float*)d_in[2];
    const float* lin1_b   = (const float*)d_in[3];
    const float* gat_w    = (const float*)d_in[4];
    const float* att_src  = (const float*)d_in[5];
    const float* att_dst  = (const float*)d_in[6];
    const float* gat_bias = (const float*)d_in[7];
    const float* dec_w    = (const float*)d_in[8];
    const float* dec_b    = (const float*)d_in[9];
    const float* ln_scale = (const float*)d_in[10];
    const float* ln_bias  = (const float*)d_in[11];
    float* out = (float*)d_out;

    cudaFuncSetAttribute(gemm_mma, cudaFuncAttributeMaxDynamicSharedMemorySize, SM_TOTAL);

    float *p_h, *p_acc3, *p_bw;
    __half *p_h1, *p_hh, *p_hl, *p_gh, *p_gl;
    int *p_deg;
    cudaGetSymbolAddress((void**)&p_h,    g_h);
    cudaGetSymbolAddress((void**)&p_h1,   g_h1);
    cudaGetSymbolAddress((void**)&p_acc3, g_acc3);
    cudaGetSymbolAddress((void**)&p_bw,   g_bw);
    cudaGetSymbolAddress((void**)&p_hh,   g_hh);
    cudaGetSymbolAddress((void**)&p_hl,   g_hl);
    cudaGetSymbolAddress((void**)&p_gh,   g_gh);
    cudaGetSymbolAddress((void**)&p_gl,   g_gl);
    cudaGetSymbolAddress((void**)&p_deg,  g_deg);

    // preamble
    cudaMemsetAsync(p_deg, 0, 3 * (size_t)Nn * sizeof(int));
    cudaMemcpyAsync(p_bw, dec_b, 6 * 256 * sizeof(float), cudaMemcpyDeviceToDevice);
    prep_kernel<<<B_PREP, 256>>>(lin1_w, gat_w, dec_w, x, gat_bias, edges);

    bsum3<<<dim3(NB, 3), 256>>>();
    bscan3<<<3, 256>>>();
    rowptr3<<<dim3(NB, 3), 256>>>();
    fill3<<<dim3((Ee + 255) / 256, 3), 256>>>(edges);

    // h = leaky(x @ lin1_w + lin1_b); writes fp32 h + h split (2-pass A)
    gemm_mma<<<dim3(NRB, 2), 256, SM_TOTAL>>>(p_gh, p_gl, 0, 0, lin1_b,
                                              nullptr, nullptr, p_h, Nn, 1 | 8, 1.f);

    for (int l = 0; l < 2; l++) {
        // all 3 hop GEMMs: h1[hop] (fp16) = h @ W[l,hop], fused alphas (2-pass A)
        gemm_mma<<<dim3(NRB, 6), 256, SM_TOTAL>>>(p_hh, p_hl, 0, 1 + l * 3, nullptr,
                                                  att_src + (size_t)l * 3 * 256,
                                                  att_dst + (size_t)l * 3 * 256,
                                                  (float*)p_h1, Nn, 4 | 32, 1.f);
        attn_csr3<<<dim3((Nn * 8 + 255) / 256, 3), 256>>>();
        edge3_csr3<<<dim3((Nn * 32 + 255) / 256, 3), 256>>>();

        // all 3 dec GEMMs: acc3[hop] = leaky(agg[hop] @ dec_w + bw); 1-pass fp16 A
        gemm_mma<<<dim3(NRB, 6), 256, SM_TOTAL>>>(p_gh, p_gl, 1, 7 + l * 3,
                                                  p_bw + l * 3 * 256,
                                                  nullptr, nullptr,
                                                  p_acc3, Nn, 1 | 16 | 64, 1.f);

        ln_kernel<<<(Nn * 32 + 255) / 256, 256>>>(
            p_acc3, ln_scale + (size_t)l * 256, ln_bias + (size_t)l * 256,
            p_h, (l == 0) ? p_h : out, (l == 0) ? 1 : 0);
    }
}